// round 3
// baseline (speedup 1.0000x reference)
#include <cuda_runtime.h>
#include <cstdint>

#define N_NODES 50000
#define NPAD    50048            // 391 * 128
#define H_DIM   128
#define F_DIM   256
#define C_DIM   40
#define CPAD    64

// ---------------------------------------------------------------------------
// Global scratch (static device globals — no allocation allowed)
// Frag layout for an MxK operand A: idx = ((row>>4)*(K/8) + (col>>3))*128
//        + ((row&7)*4 + (col&3))*4 + ((row>>3)&1) + 2*((col>>2)&1)
// Frag layout for a KxN operand B: idx = ((n>>3)*(K/8) + (k>>3))*64
//        + ((n&7)*4 + (k&3))*2 + ((k>>2)&1)
// ---------------------------------------------------------------------------
__device__ uint32_t gNF_hi[NPAD * F_DIM], gNF_lo[NPAD * F_DIM];   // n_feats split
__device__ uint32_t gX_hi [NPAD * H_DIM], gX_lo [NPAD * H_DIM];   // activation split
__device__ float    g_H[NPAD * H_DIM];     // x @ W (pre-aggregation), row-scaled
__device__ float    g_M[NPAD * H_DIM];     // aggregation accumulator
__device__ float    g_degout[NPAD];        // rsqrt(max(deg_out,1)), 1 on pad
__device__ float    g_degin [NPAD];
__device__ uint32_t gWp_hi[F_DIM * H_DIM], gWp_lo[F_DIM * H_DIM];
__device__ uint32_t gW1_hi[H_DIM * H_DIM], gW1_lo[H_DIM * H_DIM];
__device__ uint32_t gW2_hi[H_DIM * H_DIM], gW2_lo[H_DIM * H_DIM];
__device__ uint32_t gWc_hi[H_DIM * CPAD],  gWc_lo[H_DIM * CPAD];

__device__ __forceinline__ void split_tf32(float x, uint32_t& hi, uint32_t& lo) {
    uint32_t h;
    asm("cvt.rna.tf32.f32 %0, %1;" : "=r"(h) : "f"(x));
    float r = x - __uint_as_float(h);
    asm("cvt.rna.tf32.f32 %0, %1;" : "=r"(lo) : "f"(r));
    hi = h;
}

// ---------------------------------------------------------------------------
// small elementwise kernels
// ---------------------------------------------------------------------------
__global__ void zero_deg_kernel() {
    int i = blockIdx.x * blockDim.x + threadIdx.x;
    if (i < NPAD) { g_degout[i] = 0.f; g_degin[i] = 0.f; }
}

__global__ void zero_m_kernel() {
    int i = blockIdx.x * blockDim.x + threadIdx.x;
    if (i < (NPAD * H_DIM) / 4)
        reinterpret_cast<float4*>(g_M)[i] = make_float4(0.f, 0.f, 0.f, 0.f);
}

__global__ void deg_kernel(const int* __restrict__ src, const int* __restrict__ dst, int E) {
    int i = blockIdx.x * blockDim.x + threadIdx.x;
    if (i < E) {
        atomicAdd(&g_degout[src[i]], 1.f);
        atomicAdd(&g_degin[dst[i]], 1.f);
    }
}

__global__ void rsqrt_kernel() {
    int i = blockIdx.x * blockDim.x + threadIdx.x;
    if (i < NPAD) {
        g_degout[i] = rsqrtf(fmaxf(g_degout[i], 1.f));
        g_degin[i]  = rsqrtf(fmaxf(g_degin[i], 1.f));
    }
}

// Pre-split a plain row-major [N_NODES x K] matrix (pad rows -> 0) into frag-layout hi/lo
__global__ void presplit_A_kernel(const float* __restrict__ A,
                                  uint32_t* __restrict__ hi, uint32_t* __restrict__ lo, int K) {
    int perRow = K >> 2;
    int i = blockIdx.x * blockDim.x + threadIdx.x;
    if (i >= NPAD * perRow) return;
    int row = i / perRow;
    int c = (i - row * perRow) * 4;
    float4 v = make_float4(0.f, 0.f, 0.f, 0.f);
    if (row < N_NODES) v = *reinterpret_cast<const float4*>(A + (size_t)row * K + c);
    int base = ((row >> 4) * (K >> 3) + (c >> 3)) * 128 + (row & 7) * 16
             + ((row >> 3) & 1) + (((c >> 2) & 1) << 1);
    float vv[4] = {v.x, v.y, v.z, v.w};
    #pragma unroll
    for (int j = 0; j < 4; j++) {
        uint32_t h, l; split_tf32(vv[j], h, l);
        hi[base + j * 4] = h; lo[base + j * 4] = l;
    }
}

// Pre-split a weight [K x N] (cols padded to Npad with 0) into B frag layout
__global__ void presplit_W_kernel(const float* __restrict__ W,
                                  uint32_t* __restrict__ hi, uint32_t* __restrict__ lo,
                                  int K, int N, int Npad) {
    int i = blockIdx.x * blockDim.x + threadIdx.x;
    if (i >= K * Npad) return;
    int k = i / Npad, n = i - k * Npad;
    float v = (n < N) ? W[(size_t)k * N + n] : 0.f;
    int idx = ((n >> 3) * (K >> 3) + (k >> 3)) * 64 + ((n & 7) * 4 + (k & 3)) * 2 + ((k >> 2) & 1);
    uint32_t h, l; split_tf32(v, h, l);
    hi[idx] = h; lo[idx] = l;
}

// x = relu(m * rinv_in[row] + bias[col]) -> written directly as split frag layout (K=128)
__global__ void finalize_frag_kernel(const float* __restrict__ bias) {
    int i = blockIdx.x * blockDim.x + threadIdx.x;     // over NPAD * 32 float4 slots
    if (i >= NPAD * 32) return;
    int row = i >> 5;
    int c = (i & 31) * 4;
    float vv[4] = {0.f, 0.f, 0.f, 0.f};
    if (row < N_NODES) {
        float4 m = *reinterpret_cast<const float4*>(g_M + (size_t)row * H_DIM + c);
        float rs = g_degin[row];
        vv[0] = fmaxf(m.x * rs + bias[c + 0], 0.f);
        vv[1] = fmaxf(m.y * rs + bias[c + 1], 0.f);
        vv[2] = fmaxf(m.z * rs + bias[c + 2], 0.f);
        vv[3] = fmaxf(m.w * rs + bias[c + 3], 0.f);
    }
    int base = ((row >> 4) * 16 + (c >> 3)) * 128 + (row & 7) * 16
             + ((row >> 3) & 1) + (((c >> 2) & 1) << 1);
    #pragma unroll
    for (int j = 0; j < 4; j++) {
        uint32_t h, l; split_tf32(vv[j], h, l);
        gX_hi[base + j * 4] = h; gX_lo[base + j * 4] = l;
    }
}

// ---------------------------------------------------------------------------
// edge aggregation: one warp per edge, one float4 per lane; m[dst] += h[src]
// ---------------------------------------------------------------------------
__global__ void aggregate_kernel(const int* __restrict__ src, const int* __restrict__ dst, int E) {
    int warp = (blockIdx.x * blockDim.x + threadIdx.x) >> 5;
    int lane = threadIdx.x & 31;
    if (warp >= E) return;
    int s = src[warp];
    int d = dst[warp];
    float4 v = reinterpret_cast<const float4*>(g_H)[s * 32 + lane];
    float* md = g_M + (size_t)d * H_DIM + lane * 4;
    asm volatile("red.global.add.v4.f32 [%0], {%1,%2,%3,%4};"
                 :: "l"(md), "f"(v.x), "f"(v.y), "f"(v.z), "f"(v.w)
                 : "memory");
}

// ---------------------------------------------------------------------------
// 3xTF32 tensor-core GEMM, pre-split frag-layout operands.
// BM=128, BN=64, BK=32, 256 threads (8 warps, 4m x 2n), warp tile 32x32.
// cp.async 2-stage pipeline. Output: plain (guarded) or frag hi/lo.
// ---------------------------------------------------------------------------
#define STG_U 12288   // uints per stage: Ah 4096 | Al 4096 | Bh 2048 | Bl 2048

__device__ __forceinline__ void cp16(uint32_t saddr, const void* g) {
    asm volatile("cp.async.ca.shared.global [%0], [%1], 16;" :: "r"(saddr), "l"(g) : "memory");
}

__device__ __forceinline__ void mma_tf32(
    float& d0, float& d1, float& d2, float& d3,
    uint32_t a0, uint32_t a1, uint32_t a2, uint32_t a3,
    uint32_t b0, uint32_t b1)
{
    asm volatile(
        "mma.sync.aligned.m16n8k8.row.col.f32.tf32.tf32.f32 "
        "{%0,%1,%2,%3}, {%4,%5,%6,%7}, {%8,%9}, {%0,%1,%2,%3};"
        : "+f"(d0), "+f"(d1), "+f"(d2), "+f"(d3)
        : "r"(a0), "r"(a1), "r"(a2), "r"(a3), "r"(b0), "r"(b1));
}

__global__ __launch_bounds__(256) void mma_gemm_kernel(
    const uint32_t* __restrict__ Ahi, const uint32_t* __restrict__ Alo,
    const uint32_t* __restrict__ Bhi, const uint32_t* __restrict__ Blo,
    int K,
    float* __restrict__ Cplain, int ldC, int Mreal, int Nreal,
    uint32_t* __restrict__ Chi, uint32_t* __restrict__ Clo,
    const float* __restrict__ bias, const float* __restrict__ rowscale)
{
    extern __shared__ uint32_t smem_u[];
    const uint32_t smem_base = (uint32_t)__cvta_generic_to_shared(smem_u);

    const int tid  = threadIdx.x;
    const int lane = tid & 31;
    const int warp = tid >> 5;
    const int wm   = warp >> 1;
    const int wn   = warp & 1;
    const int mtile0 = blockIdx.y * 8;
    const int ntile0 = blockIdx.x * 8;
    const int kks = K >> 3;
    const int nStages = K >> 5;

    float acc[2][4][4];
    #pragma unroll
    for (int i = 0; i < 2; i++)
        #pragma unroll
        for (int j = 0; j < 4; j++)
            #pragma unroll
            for (int l = 0; l < 4; l++) acc[i][j][l] = 0.f;

    auto issue = [&](int s, int b) {
        const int kk0 = s * 4;
        const uint32_t sb = smem_base + b * (STG_U * 4);
        #pragma unroll
        for (int i = 0; i < 4; i++) {
            int s4 = tid + i * 256;
            int mt = s4 >> 7, off = s4 & 127;
            size_t g = ((size_t)(mtile0 + mt) * kks + kk0) * 32 + off;
            cp16(sb + s4 * 16,                reinterpret_cast<const uint4*>(Ahi) + g);
            cp16(sb + 4096 * 4 + s4 * 16,     reinterpret_cast<const uint4*>(Alo) + g);
        }
        #pragma unroll
        for (int i = 0; i < 2; i++) {
            int s4 = tid + i * 256;
            int nt = s4 >> 6, off = s4 & 63;
            size_t g = ((size_t)(ntile0 + nt) * kks + kk0) * 16 + off;
            cp16(sb + 8192 * 4 + s4 * 16,     reinterpret_cast<const uint4*>(Bhi) + g);
            cp16(sb + 10240 * 4 + s4 * 16,    reinterpret_cast<const uint4*>(Blo) + g);
        }
        asm volatile("cp.async.commit_group;" ::: "memory");
    };

    issue(0, 0);
    for (int s = 0; s < nStages; s++) {
        int b = s & 1;
        if (s + 1 < nStages) {
            issue(s + 1, b ^ 1);
            asm volatile("cp.async.wait_group 1;" ::: "memory");
        } else {
            asm volatile("cp.async.wait_group 0;" ::: "memory");
        }
        __syncthreads();

        const uint32_t* Ah = smem_u + b * STG_U;
        const uint32_t* Al = Ah + 4096;
        const uint32_t* Bh = Ah + 8192;
        const uint32_t* Bl = Ah + 10240;

        #pragma unroll
        for (int kk = 0; kk < 4; kk++) {
            uint4 a_h[2], a_l[2];
            #pragma unroll
            for (int mt = 0; mt < 2; mt++) {
                int mtile = wm * 2 + mt;
                a_h[mt] = *reinterpret_cast<const uint4*>(&Ah[((mtile * 4 + kk) * 32 + lane) * 4]);
                a_l[mt] = *reinterpret_cast<const uint4*>(&Al[((mtile * 4 + kk) * 32 + lane) * 4]);
            }
            uint2 b_h[4], b_l[4];
            #pragma unroll
            for (int nt = 0; nt < 4; nt++) {
                int ntile = wn * 4 + nt;
                b_h[nt] = *reinterpret_cast<const uint2*>(&Bh[((ntile * 4 + kk) * 32 + lane) * 2]);
                b_l[nt] = *reinterpret_cast<const uint2*>(&Bl[((ntile * 4 + kk) * 32 + lane) * 2]);
            }
            #pragma unroll
            for (int mt = 0; mt < 2; mt++) {
                #pragma unroll
                for (int nt = 0; nt < 4; nt++) {
                    float* d = acc[mt][nt];
                    mma_tf32(d[0], d[1], d[2], d[3],
                             a_h[mt].x, a_h[mt].y, a_h[mt].z, a_h[mt].w,
                             b_h[nt].x, b_h[nt].y);
                    mma_tf32(d[0], d[1], d[2], d[3],
                             a_l[mt].x, a_l[mt].y, a_l[mt].z, a_l[mt].w,
                             b_h[nt].x, b_h[nt].y);
                    mma_tf32(d[0], d[1], d[2], d[3],
                             a_h[mt].x, a_h[mt].y, a_h[mt].z, a_h[mt].w,
                             b_l[nt].x, b_l[nt].y);
                }
            }
        }
        __syncthreads();
    }

    // epilogue
    #pragma unroll
    for (int mt = 0; mt < 2; mt++) {
        int r0 = blockIdx.y * 128 + wm * 32 + mt * 16 + (lane >> 2);
        int r1 = r0 + 8;
        float rs0 = rowscale ? rowscale[r0] : 1.f;
        float rs1 = rowscale ? rowscale[r1] : 1.f;
        #pragma unroll
        for (int nt = 0; nt < 4; nt++) {
            int c0 = blockIdx.x * 64 + wn * 32 + nt * 8 + (lane & 3) * 2;
            #pragma unroll
            for (int half = 0; half < 2; half++) {
                int c = c0 + half;
                float bv = (bias && c < Nreal) ? bias[c] : 0.f;
                float v0 = acc[mt][nt][half]     * rs0 + bv;
                float v1 = acc[mt][nt][2 + half] * rs1 + bv;
                if (Cplain) {
                    if (c < Nreal) {
                        if (r0 < Mreal) Cplain[(size_t)r0 * ldC + c] = v0;
                        if (r1 < Mreal) Cplain[(size_t)r1 * ldC + c] = v1;
                    }
                } else {
                    uint32_t h, l;
                    int i0 = ((r0 >> 4) * 16 + (c >> 3)) * 128 + ((r0 & 7) * 4 + (c & 3)) * 4
                           + ((r0 >> 3) & 1) + (((c >> 2) & 1) << 1);
                    split_tf32(v0, h, l); Chi[i0] = h; Clo[i0] = l;
                    int i1 = ((r1 >> 4) * 16 + (c >> 3)) * 128 + ((r1 & 7) * 4 + (c & 3)) * 4
                           + ((r1 >> 3) & 1) + (((c >> 2) & 1) << 1);
                    split_tf32(v1, h, l); Chi[i1] = h; Clo[i1] = l;
                }
            }
        }
    }
}

// ---------------------------------------------------------------------------
extern "C" void kernel_launch(void* const* d_in, const int* in_sizes, int n_in,
                              void* d_out, int out_size)
{
    const float* n_feats = (const float*)d_in[0];
    const int*   src     = (const int*)  d_in[1];
    const int*   dst     = (const int*)  d_in[2];
    const float* Wp      = (const float*)d_in[3];
    const float* bp      = (const float*)d_in[4];
    const float* W1      = (const float*)d_in[5];
    const float* b1      = (const float*)d_in[6];
    const float* W2      = (const float*)d_in[7];
    const float* b2      = (const float*)d_in[8];
    const float* Wc      = (const float*)d_in[9];
    const float* bc      = (const float*)d_in[10];
    float* out = (float*)d_out;
    int E = in_sizes[1];

    uint32_t *NFhi, *NFlo, *Xhi, *Xlo, *Wphi, *Wplo, *W1hi, *W1lo, *W2hi, *W2lo, *Wchi, *Wclo;
    float *Hbuf, *degout;
    cudaGetSymbolAddress((void**)&NFhi, gNF_hi); cudaGetSymbolAddress((void**)&NFlo, gNF_lo);
    cudaGetSymbolAddress((void**)&Xhi,  gX_hi);  cudaGetSymbolAddress((void**)&Xlo,  gX_lo);
    cudaGetSymbolAddress((void**)&Wphi, gWp_hi); cudaGetSymbolAddress((void**)&Wplo, gWp_lo);
    cudaGetSymbolAddress((void**)&W1hi, gW1_hi); cudaGetSymbolAddress((void**)&W1lo, gW1_lo);
    cudaGetSymbolAddress((void**)&W2hi, gW2_hi); cudaGetSymbolAddress((void**)&W2lo, gW2_lo);
    cudaGetSymbolAddress((void**)&Wchi, gWc_hi); cudaGetSymbolAddress((void**)&Wclo, gWc_lo);
    cudaGetSymbolAddress((void**)&Hbuf, g_H);
    cudaGetSymbolAddress((void**)&degout, g_degout);

    cudaFuncSetAttribute(mma_gemm_kernel, cudaFuncAttributeMaxDynamicSharedMemorySize, 98304);

    const int T = 256;
    int nodeBlocks = (NPAD + T - 1) / T;
    int edgeBlocks = (E + T - 1) / T;
    int aggBlocks  = (E + 7) / 8;
    int fragBlocks = (NPAD * 32 + T - 1) / T;
    int zeroBlocks = (NPAD * H_DIM / 4 + T - 1) / T;
    int psFBlocks  = (NPAD * (F_DIM / 4) + T - 1) / T;

    dim3 gH(2, NPAD / 128);   // N=128 GEMMs
    dim3 gC(1, NPAD / 128);   // classifier

    // degrees -> rsqrt
    zero_deg_kernel<<<nodeBlocks, T>>>();
    deg_kernel<<<edgeBlocks, T>>>(src, dst, E);
    rsqrt_kernel<<<nodeBlocks, T>>>();

    // pre-split operands
    presplit_A_kernel<<<psFBlocks, T>>>(n_feats, NFhi, NFlo, F_DIM);
    presplit_W_kernel<<<(F_DIM * H_DIM + T - 1) / T, T>>>(Wp, Wphi, Wplo, F_DIM, H_DIM, H_DIM);
    presplit_W_kernel<<<(H_DIM * H_DIM + T - 1) / T, T>>>(W1, W1hi, W1lo, H_DIM, H_DIM, H_DIM);
    presplit_W_kernel<<<(H_DIM * H_DIM + T - 1) / T, T>>>(W2, W2hi, W2lo, H_DIM, H_DIM, H_DIM);
    presplit_W_kernel<<<(H_DIM * CPAD  + T - 1) / T, T>>>(Wc, Wchi, Wclo, H_DIM, C_DIM, CPAD);

    // projection: X = n_feats @ Wp + bp  (frag output)
    mma_gemm_kernel<<<gH, T, 98304>>>(NFhi, NFlo, Wphi, Wplo, F_DIM,
                                      nullptr, 0, 0, H_DIM, Xhi, Xlo, bp, nullptr);

    // ---- GCN layer 1 ----
    mma_gemm_kernel<<<gH, T, 98304>>>(Xhi, Xlo, W1hi, W1lo, H_DIM,
                                      Hbuf, H_DIM, NPAD, H_DIM, nullptr, nullptr, nullptr, degout);
    zero_m_kernel<<<zeroBlocks, T>>>();
    aggregate_kernel<<<aggBlocks, T>>>(src, dst, E);
    finalize_frag_kernel<<<fragBlocks, T>>>(b1);

    // ---- GCN layer 2 ----
    mma_gemm_kernel<<<gH, T, 98304>>>(Xhi, Xlo, W2hi, W2lo, H_DIM,
                                      Hbuf, H_DIM, NPAD, H_DIM, nullptr, nullptr, nullptr, degout);
    zero_m_kernel<<<zeroBlocks, T>>>();
    aggregate_kernel<<<aggBlocks, T>>>(src, dst, E);
    finalize_frag_kernel<<<fragBlocks, T>>>(b2);

    // classifier: out = X @ Wc + bc
    mma_gemm_kernel<<<gC, T, 98304>>>(Xhi, Xlo, Wchi, Wclo, H_DIM,
                                      out, C_DIM, N_NODES, C_DIM, nullptr, nullptr, bc, nullptr);
}

// round 4
// speedup vs baseline: 1.6434x; 1.6434x over previous
#include <cuda_runtime.h>
#include <cstdint>

#define N_NODES 50000
#define NPAD    50048            // 391 * 128
#define H_DIM   128
#define F_DIM   256
#define C_DIM   40
#define CPAD    64
#define E_CAP   800000

// ---------------------------------------------------------------------------
// Global scratch (static device globals)
// ---------------------------------------------------------------------------
__device__ float g_X[NPAD * H_DIM];      // activations (plain fp32)
__device__ float g_H[NPAD * H_DIM];      // x @ W, row-scaled
__device__ float g_degout[NPAD];         // rsqrt(max(deg_out,1))
__device__ float g_degin [NPAD];
__device__ int   g_cntin[NPAD], g_cntout[NPAD], g_cnt2[NPAD];
__device__ int   g_rowstart[NPAD + 1];
__device__ int   g_srcsorted[E_CAP];
// weights pre-split to tf32 hi/lo, TRANSPOSED to [N x K] row-major
__device__ uint32_t gWp_hi[H_DIM * F_DIM], gWp_lo[H_DIM * F_DIM];
__device__ uint32_t gW1_hi[H_DIM * H_DIM], gW1_lo[H_DIM * H_DIM];
__device__ uint32_t gW2_hi[H_DIM * H_DIM], gW2_lo[H_DIM * H_DIM];
__device__ uint32_t gWc_hi[CPAD  * H_DIM], gWc_lo[CPAD  * H_DIM];

__device__ __forceinline__ void split_tf32(float x, uint32_t& hi, uint32_t& lo) {
    uint32_t h;
    asm("cvt.rna.tf32.f32 %0, %1;" : "=r"(h) : "f"(x));
    float r = x - __uint_as_float(h);
    asm("cvt.rna.tf32.f32 %0, %1;" : "=r"(lo) : "f"(r));
    hi = h;
}

// ---------------------------------------------------------------------------
// CSR build + degree kernels
// ---------------------------------------------------------------------------
__global__ void zero_cnt_kernel() {
    int i = blockIdx.x * blockDim.x + threadIdx.x;
    if (i < NPAD) { g_cntin[i] = 0; g_cntout[i] = 0; g_cnt2[i] = 0; }
}

__global__ void count_kernel(const int* __restrict__ src, const int* __restrict__ dst, int E) {
    int i = blockIdx.x * blockDim.x + threadIdx.x;
    if (i < E) {
        atomicAdd(&g_cntout[src[i]], 1);
        atomicAdd(&g_cntin[dst[i]], 1);
    }
}

__global__ void rsqrt_kernel() {
    int i = blockIdx.x * blockDim.x + threadIdx.x;
    if (i < NPAD) {
        g_degout[i] = rsqrtf((float)max(g_cntout[i], 1));
        g_degin[i]  = rsqrtf((float)max(g_cntin[i], 1));
    }
}

// single-block exclusive scan of g_cntin -> g_rowstart
__global__ void scan_kernel() {
    __shared__ int part[1024];
    const int CH = 49;                       // 1024*49 = 50176 >= NPAD
    int t = threadIdx.x;
    int base = t * CH;
    int s = 0;
    #pragma unroll 4
    for (int j = 0; j < CH; j++) {
        int idx = base + j;
        if (idx < NPAD) s += g_cntin[idx];
    }
    part[t] = s;
    __syncthreads();
    for (int d = 1; d < 1024; d <<= 1) {
        int v = (t >= d) ? part[t - d] : 0;
        __syncthreads();
        part[t] += v;
        __syncthreads();
    }
    int off = (t > 0) ? part[t - 1] : 0;
    for (int j = 0; j < CH; j++) {
        int idx = base + j;
        if (idx < NPAD) { g_rowstart[idx] = off; off += g_cntin[idx]; }
    }
    if (t == 1023) g_rowstart[NPAD] = part[1023];
}

__global__ void scatter_kernel(const int* __restrict__ src, const int* __restrict__ dst, int E) {
    int i = blockIdx.x * blockDim.x + threadIdx.x;
    if (i < E) {
        int d = dst[i];
        int pos = g_rowstart[d] + atomicAdd(&g_cnt2[d], 1);
        g_srcsorted[pos] = src[i];
    }
}

// ---------------------------------------------------------------------------
// CSR aggregate + finalize: one warp per dst node.
// X[d] = relu( (sum_{e in CSR(d)} H[src_e]) * rsqrt(deg_in[d]) + bias )
// ---------------------------------------------------------------------------
__global__ void csr_agg_kernel(const float* __restrict__ bias) {
    int warp = (blockIdx.x * blockDim.x + threadIdx.x) >> 5;
    int lane = threadIdx.x & 31;
    if (warp >= NPAD) return;
    int beg = g_rowstart[warp];
    int end = g_rowstart[warp + 1];
    float4 acc = make_float4(0.f, 0.f, 0.f, 0.f);
    const float4* Hv = reinterpret_cast<const float4*>(g_H);
    int e = beg;
    for (; e + 3 < end; e += 4) {
        int s0 = g_srcsorted[e], s1 = g_srcsorted[e+1], s2 = g_srcsorted[e+2], s3 = g_srcsorted[e+3];
        float4 v0 = Hv[s0 * 32 + lane];
        float4 v1 = Hv[s1 * 32 + lane];
        float4 v2 = Hv[s2 * 32 + lane];
        float4 v3 = Hv[s3 * 32 + lane];
        acc.x += v0.x + v1.x + v2.x + v3.x;
        acc.y += v0.y + v1.y + v2.y + v3.y;
        acc.z += v0.z + v1.z + v2.z + v3.z;
        acc.w += v0.w + v1.w + v2.w + v3.w;
    }
    for (; e < end; e++) {
        float4 v = Hv[g_srcsorted[e] * 32 + lane];
        acc.x += v.x; acc.y += v.y; acc.z += v.z; acc.w += v.w;
    }
    float rs = g_degin[warp];
    float4 b = reinterpret_cast<const float4*>(bias)[lane];
    float4 x;
    x.x = fmaxf(acc.x * rs + b.x, 0.f);
    x.y = fmaxf(acc.y * rs + b.y, 0.f);
    x.z = fmaxf(acc.z * rs + b.z, 0.f);
    x.w = fmaxf(acc.w * rs + b.w, 0.f);
    reinterpret_cast<float4*>(g_X)[warp * 32 + lane] = x;
}

// ---------------------------------------------------------------------------
// weight pre-split: W[K x N] -> Wt_hi/lo[Npad x K] (transposed, zero-padded)
// ---------------------------------------------------------------------------
__global__ void presplit_Wt_kernel(const float* __restrict__ W,
                                   uint32_t* __restrict__ hi, uint32_t* __restrict__ lo,
                                   int K, int N, int Npad) {
    int i = blockIdx.x * blockDim.x + threadIdx.x;
    if (i >= Npad * K) return;
    int n = i / K, k = i - n * K;
    float v = (n < N) ? W[(size_t)k * N + n] : 0.f;
    uint32_t h, l; split_tf32(v, h, l);
    hi[i] = h; lo[i] = l;
}

// ---------------------------------------------------------------------------
// 3xTF32 GEMM: C[M,N] = A[M,K] (plain fp32) @ Wt (pre-split [N x K])
// BM=128, BN=64, BK=32, 256 threads (8 warps: 4m x 2n), warp tile 32x32.
// A: LDG -> split in regs -> STS.128 hi/lo (padded row-major) -> ldmatrix.
// B: cp.async pre-split tiles -> ldmatrix.
// ---------------------------------------------------------------------------
#define A_STR 36
#define B_STR 36
#define OFF_AL (128 * A_STR)            // 4608
#define OFF_BH (2 * 128 * A_STR)        // 9216
#define OFF_BL (OFF_BH + 64 * B_STR)    // 11520
#define STG_U  (OFF_BH + 2 * 64 * B_STR)  // 13824 uints per stage

__device__ __forceinline__ void cp16(uint32_t saddr, const void* g) {
    asm volatile("cp.async.ca.shared.global [%0], [%1], 16;" :: "r"(saddr), "l"(g) : "memory");
}

__device__ __forceinline__ void ldsm4(uint32_t& r0, uint32_t& r1, uint32_t& r2, uint32_t& r3,
                                      uint32_t saddr) {
    asm volatile("ldmatrix.sync.aligned.m8n8.x4.shared.b16 {%0,%1,%2,%3}, [%4];"
                 : "=r"(r0), "=r"(r1), "=r"(r2), "=r"(r3) : "r"(saddr));
}

__device__ __forceinline__ void mma_tf32(
    float& d0, float& d1, float& d2, float& d3,
    uint32_t a0, uint32_t a1, uint32_t a2, uint32_t a3,
    uint32_t b0, uint32_t b1)
{
    asm volatile(
        "mma.sync.aligned.m16n8k8.row.col.f32.tf32.tf32.f32 "
        "{%0,%1,%2,%3}, {%4,%5,%6,%7}, {%8,%9}, {%0,%1,%2,%3};"
        : "+f"(d0), "+f"(d1), "+f"(d2), "+f"(d3)
        : "r"(a0), "r"(a1), "r"(a2), "r"(a3), "r"(b0), "r"(b1));
}

__global__ __launch_bounds__(256) void mma_gemm_kernel(
    const float* __restrict__ A, int Mvalid,
    const uint32_t* __restrict__ Bhi, const uint32_t* __restrict__ Blo, int K,
    float* __restrict__ C, int ldC, int Mout, int Nout,
    const float* __restrict__ bias, const float* __restrict__ rowscale)
{
    extern __shared__ uint32_t smem_u[];
    const uint32_t smem_b = (uint32_t)__cvta_generic_to_shared(smem_u);

    const int tid  = threadIdx.x;
    const int lane = tid & 31;
    const int warp = tid >> 5;
    const int wm   = warp >> 1;          // 0..3
    const int wn   = warp & 1;           // 0..1
    const int rowBase = blockIdx.y * 128;
    const int colBase = blockIdx.x * 64;
    const int nStages = K >> 5;

    float acc[2][4][4];
    #pragma unroll
    for (int i = 0; i < 2; i++)
        #pragma unroll
        for (int j = 0; j < 4; j++)
            #pragma unroll
            for (int l = 0; l < 4; l++) acc[i][j][l] = 0.f;

    // A loader slots: 4 float4/thread; row = idx>>3, c4 = idx&7
    int aRow[4], aC4[4];
    #pragma unroll
    for (int i = 0; i < 4; i++) {
        int idx = tid + i * 256;
        aRow[i] = idx >> 3;
        aC4[i]  = idx & 7;
    }

    float4 pa[4];
    auto loadA = [&](int s) {
        const int k0 = s * 32;
        #pragma unroll
        for (int i = 0; i < 4; i++) {
            int gr = rowBase + aRow[i];
            pa[i] = (gr < Mvalid)
                  ? *reinterpret_cast<const float4*>(A + (size_t)gr * K + k0 + aC4[i] * 4)
                  : make_float4(0.f, 0.f, 0.f, 0.f);
        }
    };
    auto storeA = [&](int b) {
        const uint32_t sb = b * STG_U;
        #pragma unroll
        for (int i = 0; i < 4; i++) {
            uint32_t h[4], l[4];
            split_tf32(pa[i].x, h[0], l[0]);
            split_tf32(pa[i].y, h[1], l[1]);
            split_tf32(pa[i].z, h[2], l[2]);
            split_tf32(pa[i].w, h[3], l[3]);
            uint32_t off = sb + aRow[i] * A_STR + aC4[i] * 4;
            *reinterpret_cast<uint4*>(&smem_u[off])          = make_uint4(h[0], h[1], h[2], h[3]);
            *reinterpret_cast<uint4*>(&smem_u[off + OFF_AL]) = make_uint4(l[0], l[1], l[2], l[3]);
        }
    };
    auto issueB = [&](int s, int b) {
        const int k0 = s * 32;
        const uint32_t sb = smem_b + (b * STG_U) * 4;
        #pragma unroll
        for (int i = 0; i < 2; i++) {
            int s4 = tid + i * 256;          // < 512
            int n = s4 >> 3, kc4 = s4 & 7;
            size_t g = (size_t)(colBase + n) * K + k0 + kc4 * 4;
            uint32_t off = (n * B_STR + kc4 * 4) * 4;
            cp16(sb + OFF_BH * 4 + off, Bhi + g);
            cp16(sb + OFF_BL * 4 + off, Blo + g);
        }
        asm volatile("cp.async.commit_group;" ::: "memory");
    };

    loadA(0);
    issueB(0, 0);

    for (int s = 0; s < nStages; s++) {
        const int b = s & 1;
        storeA(b);
        if (s + 1 < nStages) {
            loadA(s + 1);
            issueB(s + 1, b ^ 1);
            asm volatile("cp.async.wait_group 1;" ::: "memory");
        } else {
            asm volatile("cp.async.wait_group 0;" ::: "memory");
        }
        __syncthreads();

        const uint32_t sAh = smem_b + (b * STG_U) * 4;
        const uint32_t sAl = sAh + OFF_AL * 4;
        const uint32_t sBh = sAh + OFF_BH * 4;
        const uint32_t sBl = sAh + OFF_BL * 4;
        const int m  = lane >> 3;          // matrix index 0..3
        const int lr = lane & 7;
        const int rsel = (m & 1) * 8;      // +8 rows for mats 1,3
        const int csel = (m >> 1) * 4;     // +4 cols for mats 2,3

        #pragma unroll
        for (int kk = 0; kk < 4; kk++) {
            const int kc = kk * 8 + csel;
            uint32_t ah[2][4], al[2][4];
            #pragma unroll
            for (int mt = 0; mt < 2; mt++) {
                int r = (wm * 2 + mt) * 16 + rsel + lr;
                uint32_t ad = sAh + (r * A_STR + kc) * 4;
                ldsm4(ah[mt][0], ah[mt][1], ah[mt][2], ah[mt][3], ad);
                ad = sAl + (r * A_STR + kc) * 4;
                ldsm4(al[mt][0], al[mt][1], al[mt][2], al[mt][3], ad);
            }
            uint32_t bh[2][4], bl[2][4];
            #pragma unroll
            for (int p = 0; p < 2; p++) {
                int n = wn * 32 + p * 16 + rsel + lr;
                uint32_t bd = sBh + (n * B_STR + kc) * 4;
                ldsm4(bh[p][0], bh[p][1], bh[p][2], bh[p][3], bd);
                bd = sBl + (n * B_STR + kc) * 4;
                ldsm4(bl[p][0], bl[p][1], bl[p][2], bl[p][3], bd);
            }
            #pragma unroll
            for (int mt = 0; mt < 2; mt++) {
                #pragma unroll
                for (int nt = 0; nt < 4; nt++) {
                    float* d = acc[mt][nt];
                    uint32_t b0h = bh[nt >> 1][nt & 1],  b1h = bh[nt >> 1][2 + (nt & 1)];
                    uint32_t b0l = bl[nt >> 1][nt & 1],  b1l = bl[nt >> 1][2 + (nt & 1)];
                    mma_tf32(d[0], d[1], d[2], d[3],
                             ah[mt][0], ah[mt][1], ah[mt][2], ah[mt][3], b0h, b1h);
                    mma_tf32(d[0], d[1], d[2], d[3],
                             al[mt][0], al[mt][1], al[mt][2], al[mt][3], b0h, b1h);
                    mma_tf32(d[0], d[1], d[2], d[3],
                             ah[mt][0], ah[mt][1], ah[mt][2], ah[mt][3], b0l, b1l);
                }
            }
        }
        __syncthreads();
    }

    // epilogue
    #pragma unroll
    for (int mt = 0; mt < 2; mt++) {
        int r0 = rowBase + wm * 32 + mt * 16 + (lane >> 2);
        int r1 = r0 + 8;
        float rs0 = rowscale ? rowscale[r0] : 1.f;
        float rs1 = rowscale ? rowscale[r1] : 1.f;
        #pragma unroll
        for (int nt = 0; nt < 4; nt++) {
            int c0 = colBase + wn * 32 + nt * 8 + (lane & 3) * 2;
            float b0 = (bias && c0 < Nout)     ? bias[c0]     : 0.f;
            float b1 = (bias && c0 + 1 < Nout) ? bias[c0 + 1] : 0.f;
            float v00 = acc[mt][nt][0] * rs0 + b0;
            float v01 = acc[mt][nt][1] * rs0 + b1;
            float v10 = acc[mt][nt][2] * rs1 + b0;
            float v11 = acc[mt][nt][3] * rs1 + b1;
            if (c0 + 1 < Nout) {
                if (r0 < Mout) *reinterpret_cast<float2*>(C + (size_t)r0 * ldC + c0) = make_float2(v00, v01);
                if (r1 < Mout) *reinterpret_cast<float2*>(C + (size_t)r1 * ldC + c0) = make_float2(v10, v11);
            } else if (c0 < Nout) {
                if (r0 < Mout) C[(size_t)r0 * ldC + c0] = v00;
                if (r1 < Mout) C[(size_t)r1 * ldC + c0] = v10;
            }
        }
    }
}

// ---------------------------------------------------------------------------
extern "C" void kernel_launch(void* const* d_in, const int* in_sizes, int n_in,
                              void* d_out, int out_size)
{
    const float* n_feats = (const float*)d_in[0];
    const int*   src     = (const int*)  d_in[1];
    const int*   dst     = (const int*)  d_in[2];
    const float* Wp      = (const float*)d_in[3];
    const float* bp      = (const float*)d_in[4];
    const float* W1      = (const float*)d_in[5];
    const float* b1      = (const float*)d_in[6];
    const float* W2      = (const float*)d_in[7];
    const float* b2      = (const float*)d_in[8];
    const float* Wc      = (const float*)d_in[9];
    const float* bc      = (const float*)d_in[10];
    float* out = (float*)d_out;
    int E = in_sizes[1];

    float *X, *H, *degout;
    uint32_t *Wphi, *Wplo, *W1hi, *W1lo, *W2hi, *W2lo, *Wchi, *Wclo;
    cudaGetSymbolAddress((void**)&X, g_X);
    cudaGetSymbolAddress((void**)&H, g_H);
    cudaGetSymbolAddress((void**)&degout, g_degout);
    cudaGetSymbolAddress((void**)&Wphi, gWp_hi); cudaGetSymbolAddress((void**)&Wplo, gWp_lo);
    cudaGetSymbolAddress((void**)&W1hi, gW1_hi); cudaGetSymbolAddress((void**)&W1lo, gW1_lo);
    cudaGetSymbolAddress((void**)&W2hi, gW2_hi); cudaGetSymbolAddress((void**)&W2lo, gW2_lo);
    cudaGetSymbolAddress((void**)&Wchi, gWc_hi); cudaGetSymbolAddress((void**)&Wclo, gWc_lo);

    static bool attr_set = false;
    if (!attr_set) {
        cudaFuncSetAttribute(mma_gemm_kernel, cudaFuncAttributeMaxDynamicSharedMemorySize,
                             2 * STG_U * 4);
        attr_set = true;
    }

    const int T = 256;
    int nodeBlocks = (NPAD + T - 1) / T;
    int edgeBlocks = (E + T - 1) / T;
    int aggBlocks  = (NPAD + 7) / 8;      // 8 warps/block, 1 warp/node
    const int SMEM = 2 * STG_U * 4;       // 110592 B

    dim3 gH(2, NPAD / 128);
    dim3 gC(1, NPAD / 128);

    // CSR + degrees
    zero_cnt_kernel<<<nodeBlocks, T>>>();
    count_kernel<<<edgeBlocks, T>>>(src, dst, E);
    rsqrt_kernel<<<nodeBlocks, T>>>();
    scan_kernel<<<1, 1024>>>();
    scatter_kernel<<<edgeBlocks, T>>>(src, dst, E);

    // weight pre-split (tiny)
    presplit_Wt_kernel<<<(H_DIM * F_DIM + T - 1) / T, T>>>(Wp, Wphi, Wplo, F_DIM, H_DIM, H_DIM);
    presplit_Wt_kernel<<<(H_DIM * H_DIM + T - 1) / T, T>>>(W1, W1hi, W1lo, H_DIM, H_DIM, H_DIM);
    presplit_Wt_kernel<<<(H_DIM * H_DIM + T - 1) / T, T>>>(W2, W2hi, W2lo, H_DIM, H_DIM, H_DIM);
    presplit_Wt_kernel<<<(CPAD  * H_DIM + T - 1) / T, T>>>(Wc, Wchi, Wclo, H_DIM, C_DIM, CPAD);

    // projection: X = n_feats @ Wp + bp
    mma_gemm_kernel<<<gH, T, SMEM>>>(n_feats, N_NODES, Wphi, Wplo, F_DIM,
                                     X, H_DIM, NPAD, H_DIM, bp, nullptr);

    // ---- GCN layer 1 ----
    mma_gemm_kernel<<<gH, T, SMEM>>>(X, NPAD, W1hi, W1lo, H_DIM,
                                     H, H_DIM, NPAD, H_DIM, nullptr, degout);
    csr_agg_kernel<<<aggBlocks, T>>>(b1);

    // ---- GCN layer 2 ----
    mma_gemm_kernel<<<gH, T, SMEM>>>(X, NPAD, W2hi, W2lo, H_DIM,
                                     H, H_DIM, NPAD, H_DIM, nullptr, degout);
    csr_agg_kernel<<<aggBlocks, T>>>(b2);

    // classifier: out = X @ Wc + bc
    mma_gemm_kernel<<<gC, T, SMEM>>>(X, NPAD, Wchi, Wclo, H_DIM,
                                     out, C_DIM, N_NODES, C_DIM, bc, nullptr);
}

// round 6
// speedup vs baseline: 1.8803x; 1.1442x over previous
#include <cuda_runtime.h>
#include <cstdint>

#define N_NODES 50000
#define NPAD    50048            // 391 * 128
#define H_DIM   128
#define F_DIM   256
#define C_DIM   40
#define CPAD    64
#define E_CAP   800000
#define SCAN_B  196              // ceil(NPAD / 256)

// ---------------------------------------------------------------------------
// Global scratch (static device globals)
// ---------------------------------------------------------------------------
__device__ float g_X[NPAD * H_DIM];      // activations (plain fp32)
__device__ float g_H[NPAD * H_DIM];      // x @ W, row-scaled
__device__ float g_degout[NPAD];         // rsqrt(max(deg_out,1))
__device__ float g_degin [NPAD];
__device__ int   g_cntin[NPAD], g_cntout[NPAD], g_cnt2[NPAD];
__device__ int   g_rowstart[NPAD + 1];
__device__ int   g_srcsorted[E_CAP];
__device__ int   g_blocksum[SCAN_B];
__device__ int   g_blockoff[SCAN_B];
// weights pre-split to tf32 hi/lo, TRANSPOSED to [N x K] row-major
__device__ uint32_t gWp_hi[H_DIM * F_DIM], gWp_lo[H_DIM * F_DIM];
__device__ uint32_t gW1_hi[H_DIM * H_DIM], gW1_lo[H_DIM * H_DIM];
__device__ uint32_t gW2_hi[H_DIM * H_DIM], gW2_lo[H_DIM * H_DIM];
__device__ uint32_t gWc_hi[CPAD  * H_DIM], gWc_lo[CPAD  * H_DIM];

__device__ __forceinline__ void split_tf32(float x, uint32_t& hi, uint32_t& lo) {
    uint32_t h;
    asm("cvt.rna.tf32.f32 %0, %1;" : "=r"(h) : "f"(x));
    float r = x - __uint_as_float(h);
    asm("cvt.rna.tf32.f32 %0, %1;" : "=r"(lo) : "f"(r));
    hi = h;
}

// ---------------------------------------------------------------------------
// CSR build + degree kernels
// ---------------------------------------------------------------------------
__global__ void zero_cnt_kernel() {
    int i = blockIdx.x * blockDim.x + threadIdx.x;
    if (i < NPAD) { g_cntin[i] = 0; g_cntout[i] = 0; g_cnt2[i] = 0; }
}

__global__ void count_kernel(const int* __restrict__ src, const int* __restrict__ dst, int E) {
    int i = blockIdx.x * blockDim.x + threadIdx.x;
    if (i < E) {
        atomicAdd(&g_cntout[src[i]], 1);
        atomicAdd(&g_cntin[dst[i]], 1);
    }
}

__global__ void rsqrt_kernel() {
    int i = blockIdx.x * blockDim.x + threadIdx.x;
    if (i < NPAD) {
        g_degout[i] = rsqrtf((float)max(g_cntout[i], 1));
        g_degin[i]  = rsqrtf((float)max(g_cntin[i], 1));
    }
}

// ---- 3-phase multi-block exclusive scan of g_cntin -> g_rowstart ----------
__global__ void scan_phaseA() {          // grid SCAN_B, block 256
    int t = threadIdx.x;
    int idx = blockIdx.x * 256 + t;
    int v = (idx < NPAD) ? g_cntin[idx] : 0;
    #pragma unroll
    for (int o = 16; o; o >>= 1) v += __shfl_down_sync(0xffffffffu, v, o);
    __shared__ int ws[8];
    if ((t & 31) == 0) ws[t >> 5] = v;
    __syncthreads();
    if (t < 8) {
        int s = ws[t];
        #pragma unroll
        for (int o = 4; o; o >>= 1) s += __shfl_down_sync(0xffu, s, o);
        if (t == 0) g_blocksum[blockIdx.x] = s;
    }
}

__global__ void scan_phaseB() {          // 1 block, 256 threads
    int t = threadIdx.x;
    int lane = t & 31, w = t >> 5;
    int v = (t < SCAN_B) ? g_blocksum[t] : 0;
    int x = v;
    #pragma unroll
    for (int o = 1; o < 32; o <<= 1) {
        int y = __shfl_up_sync(0xffffffffu, x, o);
        if (lane >= o) x += y;
    }
    __shared__ int ws[8];
    if (lane == 31) ws[w] = x;
    __syncthreads();
    if (t == 0) {
        int s = 0;
        #pragma unroll
        for (int i = 0; i < 8; i++) { int tmp = ws[i]; ws[i] = s; s += tmp; }
    }
    __syncthreads();
    int incl = x + ws[w];
    if (t < SCAN_B) {
        g_blockoff[t] = incl - v;               // exclusive block offset
        if (t == SCAN_B - 1) g_rowstart[NPAD] = incl;
    }
}

__global__ void scan_phaseC() {          // grid SCAN_B, block 256
    int t = threadIdx.x;
    int idx = blockIdx.x * 256 + t;
    int lane = t & 31, w = t >> 5;
    int v = (idx < NPAD) ? g_cntin[idx] : 0;
    int x = v;
    #pragma unroll
    for (int o = 1; o < 32; o <<= 1) {
        int y = __shfl_up_sync(0xffffffffu, x, o);
        if (lane >= o) x += y;
    }
    __shared__ int ws[8];
    if (lane == 31) ws[w] = x;
    __syncthreads();
    if (t == 0) {
        int s = 0;
        #pragma unroll
        for (int i = 0; i < 8; i++) { int tmp = ws[i]; ws[i] = s; s += tmp; }
    }
    __syncthreads();
    int excl = x - v + ws[w] + g_blockoff[blockIdx.x];
    if (idx < NPAD) g_rowstart[idx] = excl;
}

__global__ void scatter_kernel(const int* __restrict__ src, const int* __restrict__ dst, int E) {
    int i = blockIdx.x * blockDim.x + threadIdx.x;
    if (i < E) {
        int d = dst[i];
        int pos = g_rowstart[d] + atomicAdd(&g_cnt2[d], 1);
        g_srcsorted[pos] = src[i];
    }
}

// ---------------------------------------------------------------------------
// CSR aggregate + finalize: one warp per dst node.
// X[d] = relu( (sum_{e in CSR(d)} H[src_e]) * rsqrt(deg_in[d]) + bias )
// ---------------------------------------------------------------------------
__global__ void csr_agg_kernel(const float* __restrict__ bias) {
    int warp = (blockIdx.x * blockDim.x + threadIdx.x) >> 5;
    int lane = threadIdx.x & 31;
    if (warp >= NPAD) return;
    int beg = g_rowstart[warp];
    int end = g_rowstart[warp + 1];
    float4 acc = make_float4(0.f, 0.f, 0.f, 0.f);
    const float4* Hv = reinterpret_cast<const float4*>(g_H);
    int e = beg;
    for (; e + 3 < end; e += 4) {
        int s0 = g_srcsorted[e], s1 = g_srcsorted[e+1], s2 = g_srcsorted[e+2], s3 = g_srcsorted[e+3];
        float4 v0 = Hv[s0 * 32 + lane];
        float4 v1 = Hv[s1 * 32 + lane];
        float4 v2 = Hv[s2 * 32 + lane];
        float4 v3 = Hv[s3 * 32 + lane];
        acc.x += v0.x + v1.x + v2.x + v3.x;
        acc.y += v0.y + v1.y + v2.y + v3.y;
        acc.z += v0.z + v1.z + v2.z + v3.z;
        acc.w += v0.w + v1.w + v2.w + v3.w;
    }
    for (; e < end; e++) {
        float4 v = Hv[g_srcsorted[e] * 32 + lane];
        acc.x += v.x; acc.y += v.y; acc.z += v.z; acc.w += v.w;
    }
    float rs = g_degin[warp];
    float4 b = reinterpret_cast<const float4*>(bias)[lane];
    float4 x;
    x.x = fmaxf(acc.x * rs + b.x, 0.f);
    x.y = fmaxf(acc.y * rs + b.y, 0.f);
    x.z = fmaxf(acc.z * rs + b.z, 0.f);
    x.w = fmaxf(acc.w * rs + b.w, 0.f);
    reinterpret_cast<float4*>(g_X)[warp * 32 + lane] = x;
}

// ---------------------------------------------------------------------------
// weight pre-split: W[K x N] -> Wt_hi/lo[Npad x K] (transposed, zero-padded)
// ---------------------------------------------------------------------------
__global__ void presplit_Wt_kernel(const float* __restrict__ W,
                                   uint32_t* __restrict__ hi, uint32_t* __restrict__ lo,
                                   int K, int N, int Npad) {
    int i = blockIdx.x * blockDim.x + threadIdx.x;
    if (i >= Npad * K) return;
    int n = i / K, k = i - n * K;
    float v = (n < N) ? W[(size_t)k * N + n] : 0.f;
    uint32_t h, l; split_tf32(v, h, l);
    hi[i] = h; lo[i] = l;
}

// ---------------------------------------------------------------------------
// 3xTF32 GEMM: C[M,N] = A[M,K] (plain fp32) @ Wt (pre-split [N x K])
// BM=128, BN=64, BK=32, 256 threads (8 warps: 4m x 2n), warp tile 32x32.
// A: LDG -> split in regs -> STS.128 hi/lo (padded row-major) -> ldmatrix.
// B: cp.async pre-split tiles -> ldmatrix.
// ---------------------------------------------------------------------------
#define A_STR 36
#define B_STR 36
#define OFF_AL (128 * A_STR)            // 4608
#define OFF_BH (2 * 128 * A_STR)        // 9216
#define OFF_BL (OFF_BH + 64 * B_STR)    // 11520
#define STG_U  (OFF_BH + 2 * 64 * B_STR)  // 13824 uints per stage

__device__ __forceinline__ void cp16(uint32_t saddr, const void* g) {
    asm volatile("cp.async.ca.shared.global [%0], [%1], 16;" :: "r"(saddr), "l"(g) : "memory");
}

__device__ __forceinline__ void ldsm4(uint32_t& r0, uint32_t& r1, uint32_t& r2, uint32_t& r3,
                                      uint32_t saddr) {
    asm volatile("ldmatrix.sync.aligned.m8n8.x4.shared.b16 {%0,%1,%2,%3}, [%4];"
                 : "=r"(r0), "=r"(r1), "=r"(r2), "=r"(r3) : "r"(saddr));
}

__device__ __forceinline__ void mma_tf32(
    float& d0, float& d1, float& d2, float& d3,
    uint32_t a0, uint32_t a1, uint32_t a2, uint32_t a3,
    uint32_t b0, uint32_t b1)
{
    asm volatile(
        "mma.sync.aligned.m16n8k8.row.col.f32.tf32.tf32.f32 "
        "{%0,%1,%2,%3}, {%4,%5,%6,%7}, {%8,%9}, {%0,%1,%2,%3};"
        : "+f"(d0), "+f"(d1), "+f"(d2), "+f"(d3)
        : "r"(a0), "r"(a1), "r"(a2), "r"(a3), "r"(b0), "r"(b1));
}

__global__ __launch_bounds__(256) void mma_gemm_kernel(
    const float* __restrict__ A, int Mvalid,
    const uint32_t* __restrict__ Bhi, const uint32_t* __restrict__ Blo, int K,
    float* __restrict__ C, int ldC, int Mout, int Nout,
    const float* __restrict__ bias, const float* __restrict__ rowscale)
{
    extern __shared__ uint32_t smem_u[];
    const uint32_t smem_b = (uint32_t)__cvta_generic_to_shared(smem_u);

    const int tid  = threadIdx.x;
    const int lane = tid & 31;
    const int warp = tid >> 5;
    const int wm   = warp >> 1;          // 0..3
    const int wn   = warp & 1;           // 0..1
    const int rowBase = blockIdx.y * 128;
    const int colBase = blockIdx.x * 64;
    const int nStages = K >> 5;

    float acc[2][4][4];
    #pragma unroll
    for (int i = 0; i < 2; i++)
        #pragma unroll
        for (int j = 0; j < 4; j++)
            #pragma unroll
            for (int l = 0; l < 4; l++) acc[i][j][l] = 0.f;

    // A loader slots: 4 float4/thread; row = idx>>3, c4 = idx&7
    int aRow[4], aC4[4];
    #pragma unroll
    for (int i = 0; i < 4; i++) {
        int idx = tid + i * 256;
        aRow[i] = idx >> 3;
        aC4[i]  = idx & 7;
    }

    float4 pa[4];
    auto loadA = [&](int s) {
        const int k0 = s * 32;
        #pragma unroll
        for (int i = 0; i < 4; i++) {
            int gr = rowBase + aRow[i];
            pa[i] = (gr < Mvalid)
                  ? *reinterpret_cast<const float4*>(A + (size_t)gr * K + k0 + aC4[i] * 4)
                  : make_float4(0.f, 0.f, 0.f, 0.f);
        }
    };
    auto storeA = [&](int b) {
        const uint32_t sb = b * STG_U;
        #pragma unroll
        for (int i = 0; i < 4; i++) {
            uint32_t h[4], l[4];
            split_tf32(pa[i].x, h[0], l[0]);
            split_tf32(pa[i].y, h[1], l[1]);
            split_tf32(pa[i].z, h[2], l[2]);
            split_tf32(pa[i].w, h[3], l[3]);
            uint32_t off = sb + aRow[i] * A_STR + aC4[i] * 4;
            *reinterpret_cast<uint4*>(&smem_u[off])          = make_uint4(h[0], h[1], h[2], h[3]);
            *reinterpret_cast<uint4*>(&smem_u[off + OFF_AL]) = make_uint4(l[0], l[1], l[2], l[3]);
        }
    };
    auto issueB = [&](int s, int b) {
        const int k0 = s * 32;
        const uint32_t sb = smem_b + (b * STG_U) * 4;
        #pragma unroll
        for (int i = 0; i < 2; i++) {
            int s4 = tid + i * 256;          // < 512
            int n = s4 >> 3, kc4 = s4 & 7;
            size_t g = (size_t)(colBase + n) * K + k0 + kc4 * 4;
            uint32_t off = (n * B_STR + kc4 * 4) * 4;
            cp16(sb + OFF_BH * 4 + off, Bhi + g);
            cp16(sb + OFF_BL * 4 + off, Blo + g);
        }
        asm volatile("cp.async.commit_group;" ::: "memory");
    };

    loadA(0);
    issueB(0, 0);

    for (int s = 0; s < nStages; s++) {
        const int b = s & 1;
        storeA(b);
        if (s + 1 < nStages) {
            loadA(s + 1);
            issueB(s + 1, b ^ 1);
            asm volatile("cp.async.wait_group 1;" ::: "memory");
        } else {
            asm volatile("cp.async.wait_group 0;" ::: "memory");
        }
        __syncthreads();

        const uint32_t sAh = smem_b + (b * STG_U) * 4;
        const uint32_t sAl = sAh + OFF_AL * 4;
        const uint32_t sBh = sAh + OFF_BH * 4;
        const uint32_t sBl = sAh + OFF_BL * 4;
        const int m  = lane >> 3;          // matrix index 0..3
        const int lr = lane & 7;
        const int rsel = (m & 1) * 8;      // +8 rows for mats 1,3
        const int csel = (m >> 1) * 4;     // +4 cols for mats 2,3

        #pragma unroll
        for (int kk = 0; kk < 4; kk++) {
            const int kc = kk * 8 + csel;
            uint32_t ah[2][4], al[2][4];
            #pragma unroll
            for (int mt = 0; mt < 2; mt++) {
                int r = (wm * 2 + mt) * 16 + rsel + lr;
                uint32_t ad = sAh + (r * A_STR + kc) * 4;
                ldsm4(ah[mt][0], ah[mt][1], ah[mt][2], ah[mt][3], ad);
                ad = sAl + (r * A_STR + kc) * 4;
                ldsm4(al[mt][0], al[mt][1], al[mt][2], al[mt][3], ad);
            }
            uint32_t bh[2][4], bl[2][4];
            #pragma unroll
            for (int p = 0; p < 2; p++) {
                int n = wn * 32 + p * 16 + rsel + lr;
                uint32_t bd = sBh + (n * B_STR + kc) * 4;
                ldsm4(bh[p][0], bh[p][1], bh[p][2], bh[p][3], bd);
                bd = sBl + (n * B_STR + kc) * 4;
                ldsm4(bl[p][0], bl[p][1], bl[p][2], bl[p][3], bd);
            }
            #pragma unroll
            for (int mt = 0; mt < 2; mt++) {
                #pragma unroll
                for (int nt = 0; nt < 4; nt++) {
                    float* d = acc[mt][nt];
                    uint32_t b0h = bh[nt >> 1][nt & 1],  b1h = bh[nt >> 1][2 + (nt & 1)];
                    uint32_t b0l = bl[nt >> 1][nt & 1],  b1l = bl[nt >> 1][2 + (nt & 1)];
                    mma_tf32(d[0], d[1], d[2], d[3],
                             ah[mt][0], ah[mt][1], ah[mt][2], ah[mt][3], b0h, b1h);
                    mma_tf32(d[0], d[1], d[2], d[3],
                             al[mt][0], al[mt][1], al[mt][2], al[mt][3], b0h, b1h);
                    mma_tf32(d[0], d[1], d[2], d[3],
                             ah[mt][0], ah[mt][1], ah[mt][2], ah[mt][3], b0l, b1l);
                }
            }
        }
        __syncthreads();
    }

    // epilogue
    #pragma unroll
    for (int mt = 0; mt < 2; mt++) {
        int r0 = rowBase + wm * 32 + mt * 16 + (lane >> 2);
        int r1 = r0 + 8;
        float rs0 = rowscale ? rowscale[r0] : 1.f;
        float rs1 = rowscale ? rowscale[r1] : 1.f;
        #pragma unroll
        for (int nt = 0; nt < 4; nt++) {
            int c0 = colBase + wn * 32 + nt * 8 + (lane & 3) * 2;
            float b0 = (bias && c0 < Nout)     ? bias[c0]     : 0.f;
            float b1 = (bias && c0 + 1 < Nout) ? bias[c0 + 1] : 0.f;
            float v00 = acc[mt][nt][0] * rs0 + b0;
            float v01 = acc[mt][nt][1] * rs0 + b1;
            float v10 = acc[mt][nt][2] * rs1 + b0;
            float v11 = acc[mt][nt][3] * rs1 + b1;
            if (c0 + 1 < Nout) {
                if (r0 < Mout) *reinterpret_cast<float2*>(C + (size_t)r0 * ldC + c0) = make_float2(v00, v01);
                if (r1 < Mout) *reinterpret_cast<float2*>(C + (size_t)r1 * ldC + c0) = make_float2(v10, v11);
            } else if (c0 < Nout) {
                if (r0 < Mout) C[(size_t)r0 * ldC + c0] = v00;
                if (r1 < Mout) C[(size_t)r1 * ldC + c0] = v10;
            }
        }
    }
}

// ---------------------------------------------------------------------------
extern "C" void kernel_launch(void* const* d_in, const int* in_sizes, int n_in,
                              void* d_out, int out_size)
{
    const float* n_feats = (const float*)d_in[0];
    const int*   src     = (const int*)  d_in[1];
    const int*   dst     = (const int*)  d_in[2];
    const float* Wp      = (const float*)d_in[3];
    const float* bp      = (const float*)d_in[4];
    const float* W1      = (const float*)d_in[5];
    const float* b1      = (const float*)d_in[6];
    const float* W2      = (const float*)d_in[7];
    const float* b2      = (const float*)d_in[8];
    const float* Wc      = (const float*)d_in[9];
    const float* bc      = (const float*)d_in[10];
    float* out = (float*)d_out;
    int E = in_sizes[1];

    float *X, *H, *degout;
    uint32_t *Wphi, *Wplo, *W1hi, *W1lo, *W2hi, *W2lo, *Wchi, *Wclo;
    cudaGetSymbolAddress((void**)&X, g_X);
    cudaGetSymbolAddress((void**)&H, g_H);
    cudaGetSymbolAddress((void**)&degout, g_degout);
    cudaGetSymbolAddress((void**)&Wphi, gWp_hi); cudaGetSymbolAddress((void**)&Wplo, gWp_lo);
    cudaGetSymbolAddress((void**)&W1hi, gW1_hi); cudaGetSymbolAddress((void**)&W1lo, gW1_lo);
    cudaGetSymbolAddress((void**)&W2hi, gW2_hi); cudaGetSymbolAddress((void**)&W2lo, gW2_lo);
    cudaGetSymbolAddress((void**)&Wchi, gWc_hi); cudaGetSymbolAddress((void**)&Wclo, gWc_lo);

    static bool attr_set = false;
    if (!attr_set) {
        cudaFuncSetAttribute(mma_gemm_kernel, cudaFuncAttributeMaxDynamicSharedMemorySize,
                             2 * STG_U * 4);
        attr_set = true;
    }

    const int T = 256;
    int nodeBlocks = (NPAD + T - 1) / T;
    int edgeBlocks = (E + T - 1) / T;
    int aggBlocks  = (NPAD + 7) / 8;      // 8 warps/block, 1 warp/node
    const int SMEM = 2 * STG_U * 4;       // 110592 B

    dim3 gH(2, NPAD / 128);
    dim3 gC(1, NPAD / 128);

    // CSR + degrees
    zero_cnt_kernel<<<nodeBlocks, T>>>();
    count_kernel<<<edgeBlocks, T>>>(src, dst, E);
    rsqrt_kernel<<<nodeBlocks, T>>>();
    scan_phaseA<<<SCAN_B, T>>>();
    scan_phaseB<<<1, T>>>();
    scan_phaseC<<<SCAN_B, T>>>();
    scatter_kernel<<<edgeBlocks, T>>>(src, dst, E);

    // weight pre-split (tiny)
    presplit_Wt_kernel<<<(H_DIM * F_DIM + T - 1) / T, T>>>(Wp, Wphi, Wplo, F_DIM, H_DIM, H_DIM);
    presplit_Wt_kernel<<<(H_DIM * H_DIM + T - 1) / T, T>>>(W1, W1hi, W1lo, H_DIM, H_DIM, H_DIM);
    presplit_Wt_kernel<<<(H_DIM * H_DIM + T - 1) / T, T>>>(W2, W2hi, W2lo, H_DIM, H_DIM, H_DIM);
    presplit_Wt_kernel<<<(CPAD  * H_DIM + T - 1) / T, T>>>(Wc, Wchi, Wclo, H_DIM, C_DIM, CPAD);

    // projection: X = n_feats @ Wp + bp
    mma_gemm_kernel<<<gH, T, SMEM>>>(n_feats, N_NODES, Wphi, Wplo, F_DIM,
                                     X, H_DIM, NPAD, H_DIM, bp, nullptr);

    // ---- GCN layer 1 ----
    mma_gemm_kernel<<<gH, T, SMEM>>>(X, NPAD, W1hi, W1lo, H_DIM,
                                     H, H_DIM, NPAD, H_DIM, nullptr, degout);
    csr_agg_kernel<<<aggBlocks, T>>>(b1);

    // ---- GCN layer 2 ----
    mma_gemm_kernel<<<gH, T, SMEM>>>(X, NPAD, W2hi, W2lo, H_DIM,
                                     H, H_DIM, NPAD, H_DIM, nullptr, degout);
    csr_agg_kernel<<<aggBlocks, T>>>(b2);

    // classifier: out = X @ Wc + bc
    mma_gemm_kernel<<<gC, T, SMEM>>>(X, NPAD, Wchi, Wclo, H_DIM,
                                     out, C_DIM, N_NODES, C_DIM, bc, nullptr);
}

// round 7
// speedup vs baseline: 1.9419x; 1.0328x over previous
#include <cuda_runtime.h>
#include <cstdint>

#define N_NODES 50000
#define NPAD    50048            // 391 * 128
#define H_DIM   128
#define F_DIM   256
#define C_DIM   40
#define CPAD    64
#define E_CAP   800000
#define SCAN_B  196              // ceil(NPAD / 256)

// ---------------------------------------------------------------------------
// Global scratch (static device globals)
// ---------------------------------------------------------------------------
__device__ float g_X[NPAD * H_DIM];      // activations (plain fp32)
__device__ float g_H[NPAD * H_DIM];      // x @ W, row-scaled
__device__ float g_degout[NPAD];         // rsqrt(max(deg_out,1))
__device__ float g_degin [NPAD];
__device__ int   g_cntin[NPAD], g_cntout[NPAD], g_cnt2[NPAD];
__device__ int   g_rowstart[NPAD + 1];
__device__ int   g_srcsorted[E_CAP];
__device__ int   g_blocksum[SCAN_B];
__device__ int   g_blockoff[SCAN_B];
// weights pre-split to tf32 hi/lo, TRANSPOSED to [N x K] row-major
__device__ uint32_t gWp_hi[H_DIM * F_DIM], gWp_lo[H_DIM * F_DIM];
__device__ uint32_t gW1_hi[H_DIM * H_DIM], gW1_lo[H_DIM * H_DIM];
__device__ uint32_t gW2_hi[H_DIM * H_DIM], gW2_lo[H_DIM * H_DIM];
__device__ uint32_t gWc_hi[CPAD  * H_DIM], gWc_lo[CPAD  * H_DIM];

__device__ __forceinline__ void split_tf32(float x, uint32_t& hi, uint32_t& lo) {
    uint32_t h;
    asm("cvt.rna.tf32.f32 %0, %1;" : "=r"(h) : "f"(x));
    float r = x - __uint_as_float(h);
    asm("cvt.rna.tf32.f32 %0, %1;" : "=r"(lo) : "f"(r));
    hi = h;
}

// ---------------------------------------------------------------------------
// CSR build + degree kernels
// ---------------------------------------------------------------------------
__global__ void zero_cnt_kernel() {
    int i = blockIdx.x * blockDim.x + threadIdx.x;
    if (i < NPAD) { g_cntin[i] = 0; g_cntout[i] = 0; g_cnt2[i] = 0; }
}

__global__ void count_kernel(const int* __restrict__ src, const int* __restrict__ dst, int E) {
    int i = blockIdx.x * blockDim.x + threadIdx.x;
    if (i < E) {
        atomicAdd(&g_cntout[src[i]], 1);
        atomicAdd(&g_cntin[dst[i]], 1);
    }
}

__global__ void rsqrt_kernel() {
    int i = blockIdx.x * blockDim.x + threadIdx.x;
    if (i < NPAD) {
        g_degout[i] = rsqrtf((float)max(g_cntout[i], 1));
        g_degin[i]  = rsqrtf((float)max(g_cntin[i], 1));
    }
}

// ---- 3-phase multi-block exclusive scan of g_cntin -> g_rowstart ----------
__global__ void scan_phaseA() {          // grid SCAN_B, block 256
    int t = threadIdx.x;
    int idx = blockIdx.x * 256 + t;
    int v = (idx < NPAD) ? g_cntin[idx] : 0;
    #pragma unroll
    for (int o = 16; o; o >>= 1) v += __shfl_down_sync(0xffffffffu, v, o);
    __shared__ int ws[8];
    if ((t & 31) == 0) ws[t >> 5] = v;
    __syncthreads();
    if (t < 8) {
        int s = ws[t];
        #pragma unroll
        for (int o = 4; o; o >>= 1) s += __shfl_down_sync(0xffu, s, o);
        if (t == 0) g_blocksum[blockIdx.x] = s;
    }
}

__global__ void scan_phaseB() {          // 1 block, 256 threads
    int t = threadIdx.x;
    int lane = t & 31, w = t >> 5;
    int v = (t < SCAN_B) ? g_blocksum[t] : 0;
    int x = v;
    #pragma unroll
    for (int o = 1; o < 32; o <<= 1) {
        int y = __shfl_up_sync(0xffffffffu, x, o);
        if (lane >= o) x += y;
    }
    __shared__ int ws[8];
    if (lane == 31) ws[w] = x;
    __syncthreads();
    if (t == 0) {
        int s = 0;
        #pragma unroll
        for (int i = 0; i < 8; i++) { int tmp = ws[i]; ws[i] = s; s += tmp; }
    }
    __syncthreads();
    int incl = x + ws[w];
    if (t < SCAN_B) {
        g_blockoff[t] = incl - v;               // exclusive block offset
        if (t == SCAN_B - 1) g_rowstart[NPAD] = incl;
    }
}

__global__ void scan_phaseC() {          // grid SCAN_B, block 256
    int t = threadIdx.x;
    int idx = blockIdx.x * 256 + t;
    int lane = t & 31, w = t >> 5;
    int v = (idx < NPAD) ? g_cntin[idx] : 0;
    int x = v;
    #pragma unroll
    for (int o = 1; o < 32; o <<= 1) {
        int y = __shfl_up_sync(0xffffffffu, x, o);
        if (lane >= o) x += y;
    }
    __shared__ int ws[8];
    if (lane == 31) ws[w] = x;
    __syncthreads();
    if (t == 0) {
        int s = 0;
        #pragma unroll
        for (int i = 0; i < 8; i++) { int tmp = ws[i]; ws[i] = s; s += tmp; }
    }
    __syncthreads();
    int excl = x - v + ws[w] + g_blockoff[blockIdx.x];
    if (idx < NPAD) g_rowstart[idx] = excl;
}

__global__ void scatter_kernel(const int* __restrict__ src, const int* __restrict__ dst, int E) {
    int i = blockIdx.x * blockDim.x + threadIdx.x;
    if (i < E) {
        int d = dst[i];
        int pos = g_rowstart[d] + atomicAdd(&g_cnt2[d], 1);
        g_srcsorted[pos] = src[i];
    }
}

// ---------------------------------------------------------------------------
// CSR aggregate + finalize: one warp per dst node.
// X[d] = relu( (sum_{e in CSR(d)} H[src_e]) * rsqrt(deg_in[d]) + bias )
// ---------------------------------------------------------------------------
__global__ void csr_agg_kernel(const float* __restrict__ bias) {
    int warp = (blockIdx.x * blockDim.x + threadIdx.x) >> 5;
    int lane = threadIdx.x & 31;
    if (warp >= NPAD) return;
    int beg = g_rowstart[warp];
    int end = g_rowstart[warp + 1];
    float4 acc = make_float4(0.f, 0.f, 0.f, 0.f);
    const float4* Hv = reinterpret_cast<const float4*>(g_H);
    int e = beg;
    for (; e + 7 < end; e += 8) {
        int s0 = g_srcsorted[e],   s1 = g_srcsorted[e+1], s2 = g_srcsorted[e+2], s3 = g_srcsorted[e+3];
        int s4 = g_srcsorted[e+4], s5 = g_srcsorted[e+5], s6 = g_srcsorted[e+6], s7 = g_srcsorted[e+7];
        float4 v0 = Hv[s0 * 32 + lane];
        float4 v1 = Hv[s1 * 32 + lane];
        float4 v2 = Hv[s2 * 32 + lane];
        float4 v3 = Hv[s3 * 32 + lane];
        float4 v4 = Hv[s4 * 32 + lane];
        float4 v5 = Hv[s5 * 32 + lane];
        float4 v6 = Hv[s6 * 32 + lane];
        float4 v7 = Hv[s7 * 32 + lane];
        acc.x += (v0.x + v1.x) + (v2.x + v3.x) + ((v4.x + v5.x) + (v6.x + v7.x));
        acc.y += (v0.y + v1.y) + (v2.y + v3.y) + ((v4.y + v5.y) + (v6.y + v7.y));
        acc.z += (v0.z + v1.z) + (v2.z + v3.z) + ((v4.z + v5.z) + (v6.z + v7.z));
        acc.w += (v0.w + v1.w) + (v2.w + v3.w) + ((v4.w + v5.w) + (v6.w + v7.w));
    }
    for (; e + 3 < end; e += 4) {
        int s0 = g_srcsorted[e], s1 = g_srcsorted[e+1], s2 = g_srcsorted[e+2], s3 = g_srcsorted[e+3];
        float4 v0 = Hv[s0 * 32 + lane];
        float4 v1 = Hv[s1 * 32 + lane];
        float4 v2 = Hv[s2 * 32 + lane];
        float4 v3 = Hv[s3 * 32 + lane];
        acc.x += (v0.x + v1.x) + (v2.x + v3.x);
        acc.y += (v0.y + v1.y) + (v2.y + v3.y);
        acc.z += (v0.z + v1.z) + (v2.z + v3.z);
        acc.w += (v0.w + v1.w) + (v2.w + v3.w);
    }
    for (; e < end; e++) {
        float4 v = Hv[g_srcsorted[e] * 32 + lane];
        acc.x += v.x; acc.y += v.y; acc.z += v.z; acc.w += v.w;
    }
    float rs = g_degin[warp];
    float4 b = reinterpret_cast<const float4*>(bias)[lane];
    float4 x;
    x.x = fmaxf(acc.x * rs + b.x, 0.f);
    x.y = fmaxf(acc.y * rs + b.y, 0.f);
    x.z = fmaxf(acc.z * rs + b.z, 0.f);
    x.w = fmaxf(acc.w * rs + b.w, 0.f);
    reinterpret_cast<float4*>(g_X)[warp * 32 + lane] = x;
}

// ---------------------------------------------------------------------------
// weight pre-split: W[K x N] -> Wt_hi/lo[Npad x K] (transposed, zero-padded)
// ---------------------------------------------------------------------------
__global__ void presplit_Wt_kernel(const float* __restrict__ W,
                                   uint32_t* __restrict__ hi, uint32_t* __restrict__ lo,
                                   int K, int N, int Npad) {
    int i = blockIdx.x * blockDim.x + threadIdx.x;
    if (i >= Npad * K) return;
    int n = i / K, k = i - n * K;
    float v = (n < N) ? W[(size_t)k * N + n] : 0.f;
    uint32_t h, l; split_tf32(v, h, l);
    hi[i] = h; lo[i] = l;
}

// ---------------------------------------------------------------------------
// 3xTF32 GEMM: C[M,N] = A[M,K] (plain fp32) @ Wt (pre-split [N x K])
// BM=128, BN=64, BK=32, 256 threads (8 warps: 4m x 2n), warp tile 32x32.
// A: LDG -> split in regs -> STS.128 hi/lo (padded row-major) -> ldmatrix.
// B: cp.async pre-split tiles -> ldmatrix.
// ---------------------------------------------------------------------------
#define A_STR 36
#define B_STR 36
#define OFF_AL (128 * A_STR)            // 4608
#define OFF_BH (2 * 128 * A_STR)        // 9216
#define OFF_BL (OFF_BH + 64 * B_STR)    // 11520
#define STG_U  (OFF_BH + 2 * 64 * B_STR)  // 13824 uints per stage

__device__ __forceinline__ void cp16(uint32_t saddr, const void* g) {
    asm volatile("cp.async.ca.shared.global [%0], [%1], 16;" :: "r"(saddr), "l"(g) : "memory");
}

__device__ __forceinline__ void ldsm4(uint32_t& r0, uint32_t& r1, uint32_t& r2, uint32_t& r3,
                                      uint32_t saddr) {
    asm volatile("ldmatrix.sync.aligned.m8n8.x4.shared.b16 {%0,%1,%2,%3}, [%4];"
                 : "=r"(r0), "=r"(r1), "=r"(r2), "=r"(r3) : "r"(saddr));
}

__device__ __forceinline__ void mma_tf32(
    float& d0, float& d1, float& d2, float& d3,
    uint32_t a0, uint32_t a1, uint32_t a2, uint32_t a3,
    uint32_t b0, uint32_t b1)
{
    asm volatile(
        "mma.sync.aligned.m16n8k8.row.col.f32.tf32.tf32.f32 "
        "{%0,%1,%2,%3}, {%4,%5,%6,%7}, {%8,%9}, {%0,%1,%2,%3};"
        : "+f"(d0), "+f"(d1), "+f"(d2), "+f"(d3)
        : "r"(a0), "r"(a1), "r"(a2), "r"(a3), "r"(b0), "r"(b1));
}

__global__ __launch_bounds__(256) void mma_gemm_kernel(
    const float* __restrict__ A, int Mvalid,
    const uint32_t* __restrict__ Bhi, const uint32_t* __restrict__ Blo, int K,
    float* __restrict__ C, int ldC, int Mout, int Nout,
    const float* __restrict__ bias, const float* __restrict__ rowscale)
{
    extern __shared__ uint32_t smem_u[];
    const uint32_t smem_b = (uint32_t)__cvta_generic_to_shared(smem_u);

    const int tid  = threadIdx.x;
    const int lane = tid & 31;
    const int warp = tid >> 5;
    const int wm   = warp >> 1;          // 0..3
    const int wn   = warp & 1;           // 0..1
    const int rowBase = blockIdx.y * 128;
    const int colBase = blockIdx.x * 64;
    const int nStages = K >> 5;

    float acc[2][4][4];
    #pragma unroll
    for (int i = 0; i < 2; i++)
        #pragma unroll
        for (int j = 0; j < 4; j++)
            #pragma unroll
            for (int l = 0; l < 4; l++) acc[i][j][l] = 0.f;

    // A loader slots: 4 float4/thread; row = idx>>3, c4 = idx&7
    int aRow[4], aC4[4];
    #pragma unroll
    for (int i = 0; i < 4; i++) {
        int idx = tid + i * 256;
        aRow[i] = idx >> 3;
        aC4[i]  = idx & 7;
    }

    float4 pa[4];
    auto loadA = [&](int s) {
        const int k0 = s * 32;
        #pragma unroll
        for (int i = 0; i < 4; i++) {
            int gr = rowBase + aRow[i];
            pa[i] = (gr < Mvalid)
                  ? *reinterpret_cast<const float4*>(A + (size_t)gr * K + k0 + aC4[i] * 4)
                  : make_float4(0.f, 0.f, 0.f, 0.f);
        }
    };
    auto storeA = [&](int b) {
        const uint32_t sb = b * STG_U;
        #pragma unroll
        for (int i = 0; i < 4; i++) {
            uint32_t h[4], l[4];
            split_tf32(pa[i].x, h[0], l[0]);
            split_tf32(pa[i].y, h[1], l[1]);
            split_tf32(pa[i].z, h[2], l[2]);
            split_tf32(pa[i].w, h[3], l[3]);
            uint32_t off = sb + aRow[i] * A_STR + aC4[i] * 4;
            *reinterpret_cast<uint4*>(&smem_u[off])          = make_uint4(h[0], h[1], h[2], h[3]);
            *reinterpret_cast<uint4*>(&smem_u[off + OFF_AL]) = make_uint4(l[0], l[1], l[2], l[3]);
        }
    };
    auto issueB = [&](int s, int b) {
        const int k0 = s * 32;
        const uint32_t sb = smem_b + (b * STG_U) * 4;
        #pragma unroll
        for (int i = 0; i < 2; i++) {
            int s4 = tid + i * 256;          // < 512
            int n = s4 >> 3, kc4 = s4 & 7;
            size_t g = (size_t)(colBase + n) * K + k0 + kc4 * 4;
            uint32_t off = (n * B_STR + kc4 * 4) * 4;
            cp16(sb + OFF_BH * 4 + off, Bhi + g);
            cp16(sb + OFF_BL * 4 + off, Blo + g);
        }
        asm volatile("cp.async.commit_group;" ::: "memory");
    };

    loadA(0);
    issueB(0, 0);

    for (int s = 0; s < nStages; s++) {
        const int b = s & 1;
        storeA(b);
        if (s + 1 < nStages) {
            loadA(s + 1);
            issueB(s + 1, b ^ 1);
            asm volatile("cp.async.wait_group 1;" ::: "memory");
        } else {
            asm volatile("cp.async.wait_group 0;" ::: "memory");
        }
        __syncthreads();

        const uint32_t sAh = smem_b + (b * STG_U) * 4;
        const uint32_t sAl = sAh + OFF_AL * 4;
        const uint32_t sBh = sAh + OFF_BH * 4;
        const uint32_t sBl = sAh + OFF_BL * 4;
        const int m  = lane >> 3;          // matrix index 0..3
        const int lr = lane & 7;
        const int rsel = (m & 1) * 8;      // +8 rows for mats 1,3
        const int csel = (m >> 1) * 4;     // +4 cols for mats 2,3

        #pragma unroll
        for (int kk = 0; kk < 4; kk++) {
            const int kc = kk * 8 + csel;
            uint32_t ah[2][4], al[2][4];
            #pragma unroll
            for (int mt = 0; mt < 2; mt++) {
                int r = (wm * 2 + mt) * 16 + rsel + lr;
                uint32_t ad = sAh + (r * A_STR + kc) * 4;
                ldsm4(ah[mt][0], ah[mt][1], ah[mt][2], ah[mt][3], ad);
                ad = sAl + (r * A_STR + kc) * 4;
                ldsm4(al[mt][0], al[mt][1], al[mt][2], al[mt][3], ad);
            }
            uint32_t bh[2][4], bl[2][4];
            #pragma unroll
            for (int p = 0; p < 2; p++) {
                int n = wn * 32 + p * 16 + rsel + lr;
                uint32_t bd = sBh + (n * B_STR + kc) * 4;
                ldsm4(bh[p][0], bh[p][1], bh[p][2], bh[p][3], bd);
                bd = sBl + (n * B_STR + kc) * 4;
                ldsm4(bl[p][0], bl[p][1], bl[p][2], bl[p][3], bd);
            }
            #pragma unroll
            for (int mt = 0; mt < 2; mt++) {
                #pragma unroll
                for (int nt = 0; nt < 4; nt++) {
                    float* d = acc[mt][nt];
                    uint32_t b0h = bh[nt >> 1][nt & 1],  b1h = bh[nt >> 1][2 + (nt & 1)];
                    uint32_t b0l = bl[nt >> 1][nt & 1],  b1l = bl[nt >> 1][2 + (nt & 1)];
                    mma_tf32(d[0], d[1], d[2], d[3],
                             ah[mt][0], ah[mt][1], ah[mt][2], ah[mt][3], b0h, b1h);
                    mma_tf32(d[0], d[1], d[2], d[3],
                             al[mt][0], al[mt][1], al[mt][2], al[mt][3], b0h, b1h);
                    mma_tf32(d[0], d[1], d[2], d[3],
                             ah[mt][0], ah[mt][1], ah[mt][2], ah[mt][3], b0l, b1l);
                }
            }
        }
        __syncthreads();
    }

    // epilogue
    #pragma unroll
    for (int mt = 0; mt < 2; mt++) {
        int r0 = rowBase + wm * 32 + mt * 16 + (lane >> 2);
        int r1 = r0 + 8;
        float rs0 = rowscale ? rowscale[r0] : 1.f;
        float rs1 = rowscale ? rowscale[r1] : 1.f;
        #pragma unroll
        for (int nt = 0; nt < 4; nt++) {
            int c0 = colBase + wn * 32 + nt * 8 + (lane & 3) * 2;
            float b0 = (bias && c0 < Nout)     ? bias[c0]     : 0.f;
            float b1 = (bias && c0 + 1 < Nout) ? bias[c0 + 1] : 0.f;
            float v00 = acc[mt][nt][0] * rs0 + b0;
            float v01 = acc[mt][nt][1] * rs0 + b1;
            float v10 = acc[mt][nt][2] * rs1 + b0;
            float v11 = acc[mt][nt][3] * rs1 + b1;
            if (c0 + 1 < Nout) {
                if (r0 < Mout) *reinterpret_cast<float2*>(C + (size_t)r0 * ldC + c0) = make_float2(v00, v01);
                if (r1 < Mout) *reinterpret_cast<float2*>(C + (size_t)r1 * ldC + c0) = make_float2(v10, v11);
            } else if (c0 < Nout) {
                if (r0 < Mout) C[(size_t)r0 * ldC + c0] = v00;
                if (r1 < Mout) C[(size_t)r1 * ldC + c0] = v10;
            }
        }
    }
}

// ---------------------------------------------------------------------------
extern "C" void kernel_launch(void* const* d_in, const int* in_sizes, int n_in,
                              void* d_out, int out_size)
{
    const float* n_feats = (const float*)d_in[0];
    const int*   src     = (const int*)  d_in[1];
    const int*   dst     = (const int*)  d_in[2];
    const float* Wp      = (const float*)d_in[3];
    const float* bp      = (const float*)d_in[4];
    const float* W1      = (const float*)d_in[5];
    const float* b1      = (const float*)d_in[6];
    const float* W2      = (const float*)d_in[7];
    const float* b2      = (const float*)d_in[8];
    const float* Wc      = (const float*)d_in[9];
    const float* bc      = (const float*)d_in[10];
    float* out = (float*)d_out;
    int E = in_sizes[1];

    float *X, *H, *degout;
    uint32_t *Wphi, *Wplo, *W1hi, *W1lo, *W2hi, *W2lo, *Wchi, *Wclo;
    cudaGetSymbolAddress((void**)&X, g_X);
    cudaGetSymbolAddress((void**)&H, g_H);
    cudaGetSymbolAddress((void**)&degout, g_degout);
    cudaGetSymbolAddress((void**)&Wphi, gWp_hi); cudaGetSymbolAddress((void**)&Wplo, gWp_lo);
    cudaGetSymbolAddress((void**)&W1hi, gW1_hi); cudaGetSymbolAddress((void**)&W1lo, gW1_lo);
    cudaGetSymbolAddress((void**)&W2hi, gW2_hi); cudaGetSymbolAddress((void**)&W2lo, gW2_lo);
    cudaGetSymbolAddress((void**)&Wchi, gWc_hi); cudaGetSymbolAddress((void**)&Wclo, gWc_lo);

    // one-time host-side setup (no device allocation)
    static bool init_done = false;
    static cudaStream_t s2 = nullptr;
    static cudaEvent_t evFork, evDeg, evCsr;
    if (!init_done) {
        cudaFuncSetAttribute(mma_gemm_kernel, cudaFuncAttributeMaxDynamicSharedMemorySize,
                             2 * STG_U * 4);
        cudaStreamCreateWithFlags(&s2, cudaStreamNonBlocking);
        cudaEventCreateWithFlags(&evFork, cudaEventDisableTiming);
        cudaEventCreateWithFlags(&evDeg,  cudaEventDisableTiming);
        cudaEventCreateWithFlags(&evCsr,  cudaEventDisableTiming);
        init_done = true;
    }

    const int T = 256;
    int nodeBlocks = (NPAD + T - 1) / T;
    int edgeBlocks = (E + T - 1) / T;
    int aggBlocks  = (NPAD + 7) / 8;      // 8 warps/block, 1 warp/node
    const int SMEM = 2 * STG_U * 4;       // 110592 B

    dim3 gH(2, NPAD / 128);
    dim3 gC(1, NPAD / 128);

    // ---- fork: CSR + degree chain on s2, GEMM chain on stream 0 ----
    cudaEventRecord(evFork, 0);
    cudaStreamWaitEvent(s2, evFork, 0);

    // s2: CSR build
    zero_cnt_kernel<<<nodeBlocks, T, 0, s2>>>();
    count_kernel<<<edgeBlocks, T, 0, s2>>>(src, dst, E);
    rsqrt_kernel<<<nodeBlocks, T, 0, s2>>>();
    cudaEventRecord(evDeg, s2);           // degout/degin ready
    scan_phaseA<<<SCAN_B, T, 0, s2>>>();
    scan_phaseB<<<1, T, 0, s2>>>();
    scan_phaseC<<<SCAN_B, T, 0, s2>>>();
    scatter_kernel<<<edgeBlocks, T, 0, s2>>>(src, dst, E);
    cudaEventRecord(evCsr, s2);           // srcsorted/rowstart ready

    // stream 0: weight pre-split (tiny) + projection GEMM (independent of CSR)
    presplit_Wt_kernel<<<(H_DIM * F_DIM + T - 1) / T, T>>>(Wp, Wphi, Wplo, F_DIM, H_DIM, H_DIM);
    presplit_Wt_kernel<<<(H_DIM * H_DIM + T - 1) / T, T>>>(W1, W1hi, W1lo, H_DIM, H_DIM, H_DIM);
    presplit_Wt_kernel<<<(H_DIM * H_DIM + T - 1) / T, T>>>(W2, W2hi, W2lo, H_DIM, H_DIM, H_DIM);
    presplit_Wt_kernel<<<(CPAD  * H_DIM + T - 1) / T, T>>>(Wc, Wchi, Wclo, H_DIM, C_DIM, CPAD);

    // projection: X = n_feats @ Wp + bp
    mma_gemm_kernel<<<gH, T, SMEM>>>(n_feats, N_NODES, Wphi, Wplo, F_DIM,
                                     X, H_DIM, NPAD, H_DIM, bp, nullptr);

    // ---- GCN layer 1 (GEMM needs degout; agg needs CSR) ----
    cudaStreamWaitEvent(0, evDeg, 0);
    mma_gemm_kernel<<<gH, T, SMEM>>>(X, NPAD, W1hi, W1lo, H_DIM,
                                     H, H_DIM, NPAD, H_DIM, nullptr, degout);
    cudaStreamWaitEvent(0, evCsr, 0);
    csr_agg_kernel<<<aggBlocks, T>>>(b1);

    // ---- GCN layer 2 ----
    mma_gemm_kernel<<<gH, T, SMEM>>>(X, NPAD, W2hi, W2lo, H_DIM,
                                     H, H_DIM, NPAD, H_DIM, nullptr, degout);
    csr_agg_kernel<<<aggBlocks, T>>>(b2);

    // classifier: out = X @ Wc + bc
    mma_gemm_kernel<<<gC, T, SMEM>>>(X, NPAD, Wchi, Wclo, H_DIM,
                                     out, C_DIM, N_NODES, C_DIM, bc, nullptr);
}

// round 8
// speedup vs baseline: 2.7970x; 1.4403x over previous
#include <cuda_runtime.h>
#include <cuda_bf16.h>
#include <cstdint>

#define N_NODES 50000
#define NPAD    50048            // 391 * 128
#define H_DIM   128
#define F_DIM   256
#define C_DIM   40
#define CPAD    64
#define E_CAP   800000
#define SCAN_B  196              // ceil(NPAD / 256)

// ---------------------------------------------------------------------------
// Global scratch (static device globals)
// ---------------------------------------------------------------------------
__device__ float g_X[NPAD * H_DIM];      // activations (plain fp32)
__device__ float g_H[NPAD * H_DIM];      // x @ W, row-scaled
__device__ float g_degout[NPAD];         // rsqrt(max(deg_out,1))
__device__ float g_degin [NPAD];
__device__ int   g_cntin[NPAD], g_cntout[NPAD], g_cnt2[NPAD];
__device__ int   g_rowstart[NPAD + 1];
__device__ int   g_srcsorted[E_CAP];
__device__ int   g_blocksum[SCAN_B];
__device__ int   g_blockoff[SCAN_B];
// weights pre-split to bf16 hi/lo, TRANSPOSED to [N x K] row-major
__device__ __nv_bfloat16 gWp_hi[H_DIM * F_DIM], gWp_lo[H_DIM * F_DIM];
__device__ __nv_bfloat16 gW1_hi[H_DIM * H_DIM], gW1_lo[H_DIM * H_DIM];
__device__ __nv_bfloat16 gW2_hi[H_DIM * H_DIM], gW2_lo[H_DIM * H_DIM];
__device__ __nv_bfloat16 gWc_hi[CPAD  * H_DIM], gWc_lo[CPAD  * H_DIM];

// ---------------------------------------------------------------------------
// CSR build + degree kernels
// ---------------------------------------------------------------------------
__global__ void zero_cnt_kernel() {
    int i = blockIdx.x * blockDim.x + threadIdx.x;
    if (i < NPAD) { g_cntin[i] = 0; g_cntout[i] = 0; g_cnt2[i] = 0; }
}

__global__ void count_kernel(const int* __restrict__ src, const int* __restrict__ dst, int E) {
    int i = blockIdx.x * blockDim.x + threadIdx.x;
    if (i < E) {
        atomicAdd(&g_cntout[src[i]], 1);
        atomicAdd(&g_cntin[dst[i]], 1);
    }
}

__global__ void rsqrt_kernel() {
    int i = blockIdx.x * blockDim.x + threadIdx.x;
    if (i < NPAD) {
        g_degout[i] = rsqrtf((float)max(g_cntout[i], 1));
        g_degin[i]  = rsqrtf((float)max(g_cntin[i], 1));
    }
}

// ---- 3-phase multi-block exclusive scan of g_cntin -> g_rowstart ----------
__global__ void scan_phaseA() {          // grid SCAN_B, block 256
    int t = threadIdx.x;
    int idx = blockIdx.x * 256 + t;
    int v = (idx < NPAD) ? g_cntin[idx] : 0;
    #pragma unroll
    for (int o = 16; o; o >>= 1) v += __shfl_down_sync(0xffffffffu, v, o);
    __shared__ int ws[8];
    if ((t & 31) == 0) ws[t >> 5] = v;
    __syncthreads();
    if (t < 8) {
        int s = ws[t];
        #pragma unroll
        for (int o = 4; o; o >>= 1) s += __shfl_down_sync(0xffu, s, o);
        if (t == 0) g_blocksum[blockIdx.x] = s;
    }
}

__global__ void scan_phaseB() {          // 1 block, 256 threads
    int t = threadIdx.x;
    int lane = t & 31, w = t >> 5;
    int v = (t < SCAN_B) ? g_blocksum[t] : 0;
    int x = v;
    #pragma unroll
    for (int o = 1; o < 32; o <<= 1) {
        int y = __shfl_up_sync(0xffffffffu, x, o);
        if (lane >= o) x += y;
    }
    __shared__ int ws[8];
    if (lane == 31) ws[w] = x;
    __syncthreads();
    if (t == 0) {
        int s = 0;
        #pragma unroll
        for (int i = 0; i < 8; i++) { int tmp = ws[i]; ws[i] = s; s += tmp; }
    }
    __syncthreads();
    int incl = x + ws[w];
    if (t < SCAN_B) {
        g_blockoff[t] = incl - v;               // exclusive block offset
        if (t == SCAN_B - 1) g_rowstart[NPAD] = incl;
    }
}

__global__ void scan_phaseC() {          // grid SCAN_B, block 256
    int t = threadIdx.x;
    int idx = blockIdx.x * 256 + t;
    int lane = t & 31, w = t >> 5;
    int v = (idx < NPAD) ? g_cntin[idx] : 0;
    int x = v;
    #pragma unroll
    for (int o = 1; o < 32; o <<= 1) {
        int y = __shfl_up_sync(0xffffffffu, x, o);
        if (lane >= o) x += y;
    }
    __shared__ int ws[8];
    if (lane == 31) ws[w] = x;
    __syncthreads();
    if (t == 0) {
        int s = 0;
        #pragma unroll
        for (int i = 0; i < 8; i++) { int tmp = ws[i]; ws[i] = s; s += tmp; }
    }
    __syncthreads();
    int excl = x - v + ws[w] + g_blockoff[blockIdx.x];
    if (idx < NPAD) g_rowstart[idx] = excl;
}

__global__ void scatter_kernel(const int* __restrict__ src, const int* __restrict__ dst, int E) {
    int i = blockIdx.x * blockDim.x + threadIdx.x;
    if (i < E) {
        int d = dst[i];
        int pos = g_rowstart[d] + atomicAdd(&g_cnt2[d], 1);
        g_srcsorted[pos] = src[i];
    }
}

// ---------------------------------------------------------------------------
// CSR aggregate + finalize: one warp per dst node.
// X[d] = relu( (sum_{e in CSR(d)} H[src_e]) * rsqrt(deg_in[d]) + bias )
// ---------------------------------------------------------------------------
__global__ void csr_agg_kernel(const float* __restrict__ bias) {
    int warp = (blockIdx.x * blockDim.x + threadIdx.x) >> 5;
    int lane = threadIdx.x & 31;
    if (warp >= NPAD) return;
    int beg = g_rowstart[warp];
    int end = g_rowstart[warp + 1];
    float4 acc = make_float4(0.f, 0.f, 0.f, 0.f);
    const float4* Hv = reinterpret_cast<const float4*>(g_H);
    int e = beg;
    for (; e + 7 < end; e += 8) {
        int s0 = g_srcsorted[e],   s1 = g_srcsorted[e+1], s2 = g_srcsorted[e+2], s3 = g_srcsorted[e+3];
        int s4 = g_srcsorted[e+4], s5 = g_srcsorted[e+5], s6 = g_srcsorted[e+6], s7 = g_srcsorted[e+7];
        float4 v0 = Hv[s0 * 32 + lane];
        float4 v1 = Hv[s1 * 32 + lane];
        float4 v2 = Hv[s2 * 32 + lane];
        float4 v3 = Hv[s3 * 32 + lane];
        float4 v4 = Hv[s4 * 32 + lane];
        float4 v5 = Hv[s5 * 32 + lane];
        float4 v6 = Hv[s6 * 32 + lane];
        float4 v7 = Hv[s7 * 32 + lane];
        acc.x += (v0.x + v1.x) + (v2.x + v3.x) + ((v4.x + v5.x) + (v6.x + v7.x));
        acc.y += (v0.y + v1.y) + (v2.y + v3.y) + ((v4.y + v5.y) + (v6.y + v7.y));
        acc.z += (v0.z + v1.z) + (v2.z + v3.z) + ((v4.z + v5.z) + (v6.z + v7.z));
        acc.w += (v0.w + v1.w) + (v2.w + v3.w) + ((v4.w + v5.w) + (v6.w + v7.w));
    }
    for (; e + 3 < end; e += 4) {
        int s0 = g_srcsorted[e], s1 = g_srcsorted[e+1], s2 = g_srcsorted[e+2], s3 = g_srcsorted[e+3];
        float4 v0 = Hv[s0 * 32 + lane];
        float4 v1 = Hv[s1 * 32 + lane];
        float4 v2 = Hv[s2 * 32 + lane];
        float4 v3 = Hv[s3 * 32 + lane];
        acc.x += (v0.x + v1.x) + (v2.x + v3.x);
        acc.y += (v0.y + v1.y) + (v2.y + v3.y);
        acc.z += (v0.z + v1.z) + (v2.z + v3.z);
        acc.w += (v0.w + v1.w) + (v2.w + v3.w);
    }
    for (; e < end; e++) {
        float4 v = Hv[g_srcsorted[e] * 32 + lane];
        acc.x += v.x; acc.y += v.y; acc.z += v.z; acc.w += v.w;
    }
    float rs = g_degin[warp];
    float4 b = reinterpret_cast<const float4*>(bias)[lane];
    float4 x;
    x.x = fmaxf(acc.x * rs + b.x, 0.f);
    x.y = fmaxf(acc.y * rs + b.y, 0.f);
    x.z = fmaxf(acc.z * rs + b.z, 0.f);
    x.w = fmaxf(acc.w * rs + b.w, 0.f);
    reinterpret_cast<float4*>(g_X)[warp * 32 + lane] = x;
}

// ---------------------------------------------------------------------------
// weight pre-split: W[K x N] -> bf16 hi/lo [Npad x K] (transposed, padded)
// ---------------------------------------------------------------------------
__global__ void presplit_Wt_kernel(const float* __restrict__ W,
                                   __nv_bfloat16* __restrict__ hi,
                                   __nv_bfloat16* __restrict__ lo,
                                   int K, int N, int Npad) {
    int i = blockIdx.x * blockDim.x + threadIdx.x;
    if (i >= Npad * K) return;
    int n = i / K, k = i - n * K;
    float v = (n < N) ? W[(size_t)k * N + n] : 0.f;
    __nv_bfloat16 h = __float2bfloat16_rn(v);
    float r = v - __bfloat162float(h);
    hi[i] = h;
    lo[i] = __float2bfloat16_rn(r);
}

// ---------------------------------------------------------------------------
// split-BF16 GEMM (3 products: hh + lh + hl): C[M,N] = A[M,K] @ Wt[N x K]
// BM=128, BN=64, BK=32, 256 threads (8 warps: 4m x 2n), warp tile 32x32.
// A: LDG fp32 -> split to bf16 hi/lo in regs -> STS -> ldmatrix.b16
// B: cp.async pre-split bf16 tiles -> ldmatrix.b16
// mma.sync.m16n8k16.bf16, fp32 accum.
// ---------------------------------------------------------------------------
#define A_STRB   40                       // bf16 units per A/B row (80 bytes)
#define OFF_AH   0
#define OFF_AL   10240                    // 128 * 80
#define OFF_BH   20480
#define OFF_BL   25600                    // + 64 * 80
#define STG_BYTES 30720
#define SMEM_TOT (2 * STG_BYTES)          // 61440

__device__ __forceinline__ void cp16(uint32_t saddr, const void* g) {
    asm volatile("cp.async.ca.shared.global [%0], [%1], 16;" :: "r"(saddr), "l"(g) : "memory");
}

__device__ __forceinline__ void ldsm4(uint32_t& r0, uint32_t& r1, uint32_t& r2, uint32_t& r3,
                                      uint32_t saddr) {
    asm volatile("ldmatrix.sync.aligned.m8n8.x4.shared.b16 {%0,%1,%2,%3}, [%4];"
                 : "=r"(r0), "=r"(r1), "=r"(r2), "=r"(r3) : "r"(saddr));
}

__device__ __forceinline__ void mma_bf16(
    float& d0, float& d1, float& d2, float& d3,
    uint32_t a0, uint32_t a1, uint32_t a2, uint32_t a3,
    uint32_t b0, uint32_t b1)
{
    asm volatile(
        "mma.sync.aligned.m16n8k16.row.col.f32.bf16.bf16.f32 "
        "{%0,%1,%2,%3}, {%4,%5,%6,%7}, {%8,%9}, {%0,%1,%2,%3};"
        : "+f"(d0), "+f"(d1), "+f"(d2), "+f"(d3)
        : "r"(a0), "r"(a1), "r"(a2), "r"(a3), "r"(b0), "r"(b1));
}

// pack two floats' bf16 hi parts / lo parts
__device__ __forceinline__ void split_pack2(float x, float y, uint32_t& hi2, uint32_t& lo2) {
    __nv_bfloat162 h = __floats2bfloat162_rn(x, y);
    float rx = x - __bfloat162float(__low2bfloat16(h));
    float ry = y - __bfloat162float(__high2bfloat16(h));
    __nv_bfloat162 l = __floats2bfloat162_rn(rx, ry);
    hi2 = *reinterpret_cast<uint32_t*>(&h);
    lo2 = *reinterpret_cast<uint32_t*>(&l);
}

__global__ __launch_bounds__(256) void mma_gemm_kernel(
    const float* __restrict__ A, int Mvalid,
    const __nv_bfloat16* __restrict__ Bhi, const __nv_bfloat16* __restrict__ Blo, int K,
    float* __restrict__ C, int ldC, int Mout, int Nout,
    const float* __restrict__ bias, const float* __restrict__ rowscale)
{
    extern __shared__ uint8_t smem_raw[];
    const uint32_t smem_b = (uint32_t)__cvta_generic_to_shared(smem_raw);

    const int tid  = threadIdx.x;
    const int lane = tid & 31;
    const int warp = tid >> 5;
    const int wm   = warp >> 1;          // 0..3
    const int wn   = warp & 1;           // 0..1
    const int rowBase = blockIdx.y * 128;
    const int colBase = blockIdx.x * 64;
    const int nStages = K >> 5;

    float acc[2][4][4];
    #pragma unroll
    for (int i = 0; i < 2; i++)
        #pragma unroll
        for (int j = 0; j < 4; j++)
            #pragma unroll
            for (int l = 0; l < 4; l++) acc[i][j][l] = 0.f;

    // A loader slots: 4 float4/thread; row = idx>>3, c4 = idx&7 (32 floats/row)
    int aRow[4], aC4[4];
    #pragma unroll
    for (int i = 0; i < 4; i++) {
        int idx = tid + i * 256;
        aRow[i] = idx >> 3;
        aC4[i]  = idx & 7;
    }
    // B loader slot: 1 per thread: n = tid>>2, c16 = tid&3 (4x16B chunks per 64B row)
    const int bN = tid >> 2, bC = tid & 3;

    float4 pa[4];
    auto loadA = [&](int s) {
        const int k0 = s * 32;
        #pragma unroll
        for (int i = 0; i < 4; i++) {
            int gr = rowBase + aRow[i];
            pa[i] = (gr < Mvalid)
                  ? *reinterpret_cast<const float4*>(A + (size_t)gr * K + k0 + aC4[i] * 4)
                  : make_float4(0.f, 0.f, 0.f, 0.f);
        }
    };
    auto storeA = [&](int b) {
        const uint32_t sb = smem_b + b * STG_BYTES;
        #pragma unroll
        for (int i = 0; i < 4; i++) {
            uint32_t h01, l01, h23, l23;
            split_pack2(pa[i].x, pa[i].y, h01, l01);
            split_pack2(pa[i].z, pa[i].w, h23, l23);
            uint32_t off = aRow[i] * 80 + aC4[i] * 8;
            uint32_t gen_h = off + b * STG_BYTES + OFF_AH;
            uint32_t gen_l = off + b * STG_BYTES + OFF_AL;
            *reinterpret_cast<uint2*>(smem_raw + gen_h) = make_uint2(h01, h23);
            *reinterpret_cast<uint2*>(smem_raw + gen_l) = make_uint2(l01, l23);
        }
        (void)sb;
    };
    auto issueB = [&](int s, int b) {
        const int k0 = s * 32;
        const uint32_t sb = smem_b + b * STG_BYTES;
        size_t g = (size_t)(colBase + bN) * K + k0 + bC * 8;
        uint32_t off = bN * 80 + bC * 16;
        cp16(sb + OFF_BH + off, Bhi + g);
        cp16(sb + OFF_BL + off, Blo + g);
        asm volatile("cp.async.commit_group;" ::: "memory");
    };

    loadA(0);
    issueB(0, 0);

    for (int s = 0; s < nStages; s++) {
        const int b = s & 1;
        storeA(b);
        if (s + 1 < nStages) {
            loadA(s + 1);
            issueB(s + 1, b ^ 1);
            asm volatile("cp.async.wait_group 1;" ::: "memory");
        } else {
            asm volatile("cp.async.wait_group 0;" ::: "memory");
        }
        __syncthreads();

        const uint32_t sAh = smem_b + b * STG_BYTES + OFF_AH;
        const uint32_t sAl = smem_b + b * STG_BYTES + OFF_AL;
        const uint32_t sBh = smem_b + b * STG_BYTES + OFF_BH;
        const uint32_t sBl = smem_b + b * STG_BYTES + OFF_BL;

        // ldmatrix lane address components
        const int aLRow = lane & 15;               // row within 16-row tile
        const int aKoff = (lane >> 4) * 8;         // +8 k for mats 2,3
        const int bLN   = ((lane >> 4) << 3) + (lane & 7);  // n within 16-col pair
        const int bKoff = ((lane >> 3) & 1) * 8;   // +8 k for mats 1,3

        #pragma unroll
        for (int kk = 0; kk < 2; kk++) {
            const int kb = kk * 16;
            uint32_t ah[2][4], al[2][4];
            #pragma unroll
            for (int mt = 0; mt < 2; mt++) {
                int r = (wm * 2 + mt) * 16 + aLRow;
                uint32_t ad = sAh + r * 80 + (kb + aKoff) * 2;
                ldsm4(ah[mt][0], ah[mt][1], ah[mt][2], ah[mt][3], ad);
                ad = sAl + r * 80 + (kb + aKoff) * 2;
                ldsm4(al[mt][0], al[mt][1], al[mt][2], al[mt][3], ad);
            }
            uint32_t bh[2][4], bl[2][4];
            #pragma unroll
            for (int p = 0; p < 2; p++) {
                int n = wn * 32 + p * 16 + bLN;
                uint32_t bd = sBh + n * 80 + (kb + bKoff) * 2;
                ldsm4(bh[p][0], bh[p][1], bh[p][2], bh[p][3], bd);
                bd = sBl + n * 80 + (kb + bKoff) * 2;
                ldsm4(bl[p][0], bl[p][1], bl[p][2], bl[p][3], bd);
            }
            #pragma unroll
            for (int mt = 0; mt < 2; mt++) {
                #pragma unroll
                for (int nt = 0; nt < 4; nt++) {
                    float* d = acc[mt][nt];
                    int p = nt >> 1, q = (nt & 1) * 2;
                    uint32_t b0h = bh[p][q], b1h = bh[p][q + 1];
                    uint32_t b0l = bl[p][q], b1l = bl[p][q + 1];
                    mma_bf16(d[0], d[1], d[2], d[3],
                             ah[mt][0], ah[mt][1], ah[mt][2], ah[mt][3], b0h, b1h);
                    mma_bf16(d[0], d[1], d[2], d[3],
                             al[mt][0], al[mt][1], al[mt][2], al[mt][3], b0h, b1h);
                    mma_bf16(d[0], d[1], d[2], d[3],
                             ah[mt][0], ah[mt][1], ah[mt][2], ah[mt][3], b0l, b1l);
                }
            }
        }
        __syncthreads();
    }

    // epilogue
    #pragma unroll
    for (int mt = 0; mt < 2; mt++) {
        int r0 = rowBase + wm * 32 + mt * 16 + (lane >> 2);
        int r1 = r0 + 8;
        float rs0 = rowscale ? rowscale[r0] : 1.f;
        float rs1 = rowscale ? rowscale[r1] : 1.f;
        #pragma unroll
        for (int nt = 0; nt < 4; nt++) {
            int c0 = colBase + wn * 32 + nt * 8 + (lane & 3) * 2;
            float b0 = (bias && c0 < Nout)     ? bias[c0]     : 0.f;
            float b1 = (bias && c0 + 1 < Nout) ? bias[c0 + 1] : 0.f;
            float v00 = acc[mt][nt][0] * rs0 + b0;
            float v01 = acc[mt][nt][1] * rs0 + b1;
            float v10 = acc[mt][nt][2] * rs1 + b0;
            float v11 = acc[mt][nt][3] * rs1 + b1;
            if (c0 + 1 < Nout) {
                if (r0 < Mout) *reinterpret_cast<float2*>(C + (size_t)r0 * ldC + c0) = make_float2(v00, v01);
                if (r1 < Mout) *reinterpret_cast<float2*>(C + (size_t)r1 * ldC + c0) = make_float2(v10, v11);
            } else if (c0 < Nout) {
                if (r0 < Mout) C[(size_t)r0 * ldC + c0] = v00;
                if (r1 < Mout) C[(size_t)r1 * ldC + c0] = v10;
            }
        }
    }
}

// ---------------------------------------------------------------------------
extern "C" void kernel_launch(void* const* d_in, const int* in_sizes, int n_in,
                              void* d_out, int out_size)
{
    const float* n_feats = (const float*)d_in[0];
    const int*   src     = (const int*)  d_in[1];
    const int*   dst     = (const int*)  d_in[2];
    const float* Wp      = (const float*)d_in[3];
    const float* bp      = (const float*)d_in[4];
    const float* W1      = (const float*)d_in[5];
    const float* b1      = (const float*)d_in[6];
    const float* W2      = (const float*)d_in[7];
    const float* b2      = (const float*)d_in[8];
    const float* Wc      = (const float*)d_in[9];
    const float* bc      = (const float*)d_in[10];
    float* out = (float*)d_out;
    int E = in_sizes[1];

    float *X, *H, *degout;
    __nv_bfloat16 *Wphi, *Wplo, *W1hi, *W1lo, *W2hi, *W2lo, *Wchi, *Wclo;
    cudaGetSymbolAddress((void**)&X, g_X);
    cudaGetSymbolAddress((void**)&H, g_H);
    cudaGetSymbolAddress((void**)&degout, g_degout);
    cudaGetSymbolAddress((void**)&Wphi, gWp_hi); cudaGetSymbolAddress((void**)&Wplo, gWp_lo);
    cudaGetSymbolAddress((void**)&W1hi, gW1_hi); cudaGetSymbolAddress((void**)&W1lo, gW1_lo);
    cudaGetSymbolAddress((void**)&W2hi, gW2_hi); cudaGetSymbolAddress((void**)&W2lo, gW2_lo);
    cudaGetSymbolAddress((void**)&Wchi, gWc_hi); cudaGetSymbolAddress((void**)&Wclo, gWc_lo);

    // one-time host-side setup (no device allocation)
    static bool init_done = false;
    static cudaStream_t s2 = nullptr;
    static cudaEvent_t evFork, evDeg, evCsr;
    if (!init_done) {
        cudaFuncSetAttribute(mma_gemm_kernel, cudaFuncAttributeMaxDynamicSharedMemorySize,
                             SMEM_TOT);
        cudaStreamCreateWithFlags(&s2, cudaStreamNonBlocking);
        cudaEventCreateWithFlags(&evFork, cudaEventDisableTiming);
        cudaEventCreateWithFlags(&evDeg,  cudaEventDisableTiming);
        cudaEventCreateWithFlags(&evCsr,  cudaEventDisableTiming);
        init_done = true;
    }

    const int T = 256;
    int nodeBlocks = (NPAD + T - 1) / T;
    int edgeBlocks = (E + T - 1) / T;
    int aggBlocks  = (NPAD + 7) / 8;      // 8 warps/block, 1 warp/node

    dim3 gH(2, NPAD / 128);
    dim3 gC(1, NPAD / 128);

    // ---- fork: CSR + degree chain on s2, GEMM chain on stream 0 ----
    cudaEventRecord(evFork, 0);
    cudaStreamWaitEvent(s2, evFork, 0);

    // s2: CSR build
    zero_cnt_kernel<<<nodeBlocks, T, 0, s2>>>();
    count_kernel<<<edgeBlocks, T, 0, s2>>>(src, dst, E);
    rsqrt_kernel<<<nodeBlocks, T, 0, s2>>>();
    cudaEventRecord(evDeg, s2);           // degout/degin ready
    scan_phaseA<<<SCAN_B, T, 0, s2>>>();
    scan_phaseB<<<1, T, 0, s2>>>();
    scan_phaseC<<<SCAN_B, T, 0, s2>>>();
    scatter_kernel<<<edgeBlocks, T, 0, s2>>>(src, dst, E);
    cudaEventRecord(evCsr, s2);           // srcsorted/rowstart ready

    // stream 0: weight pre-split (tiny) + projection GEMM (independent of CSR)
    presplit_Wt_kernel<<<(H_DIM * F_DIM + T - 1) / T, T>>>(Wp, Wphi, Wplo, F_DIM, H_DIM, H_DIM);
    presplit_Wt_kernel<<<(H_DIM * H_DIM + T - 1) / T, T>>>(W1, W1hi, W1lo, H_DIM, H_DIM, H_DIM);
    presplit_Wt_kernel<<<(H_DIM * H_DIM + T - 1) / T, T>>>(W2, W2hi, W2lo, H_DIM, H_DIM, H_DIM);
    presplit_Wt_kernel<<<(CPAD  * H_DIM + T - 1) / T, T>>>(Wc, Wchi, Wclo, H_DIM, C_DIM, CPAD);

    // projection: X = n_feats @ Wp + bp
    mma_gemm_kernel<<<gH, T, SMEM_TOT>>>(n_feats, N_NODES, Wphi, Wplo, F_DIM,
                                         X, H_DIM, NPAD, H_DIM, bp, nullptr);

    // ---- GCN layer 1 (GEMM needs degout; agg needs CSR) ----
    cudaStreamWaitEvent(0, evDeg, 0);
    mma_gemm_kernel<<<gH, T, SMEM_TOT>>>(X, NPAD, W1hi, W1lo, H_DIM,
                                         H, H_DIM, NPAD, H_DIM, nullptr, degout);
    cudaStreamWaitEvent(0, evCsr, 0);
    csr_agg_kernel<<<aggBlocks, T>>>(b1);

    // ---- GCN layer 2 ----
    mma_gemm_kernel<<<gH, T, SMEM_TOT>>>(X, NPAD, W2hi, W2lo, H_DIM,
                                         H, H_DIM, NPAD, H_DIM, nullptr, degout);
    csr_agg_kernel<<<aggBlocks, T>>>(b2);

    // classifier: out = X @ Wc + bc
    mma_gemm_kernel<<<gC, T, SMEM_TOT>>>(X, NPAD, Wchi, Wclo, H_DIM,
                                         out, C_DIM, N_NODES, C_DIM, bc, nullptr);
}

// round 9
// speedup vs baseline: 3.0423x; 1.0877x over previous
#include <cuda_runtime.h>
#include <cuda_bf16.h>
#include <cuda_fp16.h>
#include <cstdint>

#define N_NODES 50000
#define NPAD    50048            // 391 * 128
#define H_DIM   128
#define F_DIM   256
#define C_DIM   40
#define CPAD    64
#define E_CAP   800000
#define SCAN_B  196              // ceil(NPAD / 256)

// ---------------------------------------------------------------------------
// Global scratch (static device globals)
// ---------------------------------------------------------------------------
__device__ float  g_X[NPAD * H_DIM];     // activations (plain fp32)
__device__ __half g_Hh[NPAD * H_DIM];    // x @ W, row-scaled, fp16 messages
__device__ float  g_degout[NPAD];        // rsqrt(max(deg_out,1))
__device__ float  g_degin [NPAD];
__device__ int    g_cntin[NPAD], g_cntout[NPAD], g_cnt2[NPAD];
__device__ int    g_rowstart[NPAD + 1];
__device__ int    g_srcsorted[E_CAP];
__device__ int    g_blocksum[SCAN_B];
__device__ int    g_blockoff[SCAN_B];
// weights pre-split to bf16 hi/lo, TRANSPOSED to [N x K] row-major
__device__ __nv_bfloat16 gWp_hi[H_DIM * F_DIM], gWp_lo[H_DIM * F_DIM];
__device__ __nv_bfloat16 gW1_hi[H_DIM * H_DIM], gW1_lo[H_DIM * H_DIM];
__device__ __nv_bfloat16 gW2_hi[H_DIM * H_DIM], gW2_lo[H_DIM * H_DIM];
__device__ __nv_bfloat16 gWc_hi[CPAD  * H_DIM], gWc_lo[CPAD  * H_DIM];

// ---------------------------------------------------------------------------
// CSR build + degree kernels
// ---------------------------------------------------------------------------
__global__ void zero_cnt_kernel() {
    int i = blockIdx.x * blockDim.x + threadIdx.x;
    if (i < NPAD) { g_cntin[i] = 0; g_cntout[i] = 0; g_cnt2[i] = 0; }
}

__global__ void count_kernel(const int* __restrict__ src, const int* __restrict__ dst, int E) {
    int i = blockIdx.x * blockDim.x + threadIdx.x;
    if (i < E) {
        atomicAdd(&g_cntout[src[i]], 1);
        atomicAdd(&g_cntin[dst[i]], 1);
    }
}

__global__ void rsqrt_kernel() {
    int i = blockIdx.x * blockDim.x + threadIdx.x;
    if (i < NPAD) {
        g_degout[i] = rsqrtf((float)max(g_cntout[i], 1));
        g_degin[i]  = rsqrtf((float)max(g_cntin[i], 1));
    }
}

// ---- 3-phase multi-block exclusive scan of g_cntin -> g_rowstart ----------
__global__ void scan_phaseA() {          // grid SCAN_B, block 256
    int t = threadIdx.x;
    int idx = blockIdx.x * 256 + t;
    int v = (idx < NPAD) ? g_cntin[idx] : 0;
    #pragma unroll
    for (int o = 16; o; o >>= 1) v += __shfl_down_sync(0xffffffffu, v, o);
    __shared__ int ws[8];
    if ((t & 31) == 0) ws[t >> 5] = v;
    __syncthreads();
    if (t < 8) {
        int s = ws[t];
        #pragma unroll
        for (int o = 4; o; o >>= 1) s += __shfl_down_sync(0xffu, s, o);
        if (t == 0) g_blocksum[blockIdx.x] = s;
    }
}

__global__ void scan_phaseB() {          // 1 block, 256 threads
    int t = threadIdx.x;
    int lane = t & 31, w = t >> 5;
    int v = (t < SCAN_B) ? g_blocksum[t] : 0;
    int x = v;
    #pragma unroll
    for (int o = 1; o < 32; o <<= 1) {
        int y = __shfl_up_sync(0xffffffffu, x, o);
        if (lane >= o) x += y;
    }
    __shared__ int ws[8];
    if (lane == 31) ws[w] = x;
    __syncthreads();
    if (t == 0) {
        int s = 0;
        #pragma unroll
        for (int i = 0; i < 8; i++) { int tmp = ws[i]; ws[i] = s; s += tmp; }
    }
    __syncthreads();
    int incl = x + ws[w];
    if (t < SCAN_B) {
        g_blockoff[t] = incl - v;               // exclusive block offset
        if (t == SCAN_B - 1) g_rowstart[NPAD] = incl;
    }
}

__global__ void scan_phaseC() {          // grid SCAN_B, block 256
    int t = threadIdx.x;
    int idx = blockIdx.x * 256 + t;
    int lane = t & 31, w = t >> 5;
    int v = (idx < NPAD) ? g_cntin[idx] : 0;
    int x = v;
    #pragma unroll
    for (int o = 1; o < 32; o <<= 1) {
        int y = __shfl_up_sync(0xffffffffu, x, o);
        if (lane >= o) x += y;
    }
    __shared__ int ws[8];
    if (lane == 31) ws[w] = x;
    __syncthreads();
    if (t == 0) {
        int s = 0;
        #pragma unroll
        for (int i = 0; i < 8; i++) { int tmp = ws[i]; ws[i] = s; s += tmp; }
    }
    __syncthreads();
    int excl = x - v + ws[w] + g_blockoff[blockIdx.x];
    if (idx < NPAD) g_rowstart[idx] = excl;
}

__global__ void scatter_kernel(const int* __restrict__ src, const int* __restrict__ dst, int E) {
    int i = blockIdx.x * blockDim.x + threadIdx.x;
    if (i < E) {
        int d = dst[i];
        int pos = g_rowstart[d] + atomicAdd(&g_cnt2[d], 1);
        g_srcsorted[pos] = src[i];
    }
}

// ---------------------------------------------------------------------------
// CSR aggregate + finalize: one warp per dst node, fp16 messages.
// X[d] = relu( (sum_{e in CSR(d)} H[src_e]) * rsqrt(deg_in[d]) + bias )
// Each lane covers 4 feature cols (lane*4 .. lane*4+3); row = 32 uint2.
// ---------------------------------------------------------------------------
__global__ void csr_agg_kernel(const float* __restrict__ bias) {
    int warp = (blockIdx.x * blockDim.x + threadIdx.x) >> 5;
    int lane = threadIdx.x & 31;
    if (warp >= NPAD) return;
    int beg = g_rowstart[warp];
    int end = g_rowstart[warp + 1];
    float4 acc = make_float4(0.f, 0.f, 0.f, 0.f);
    const uint2* Hv = reinterpret_cast<const uint2*>(g_Hh);

    auto addrow = [&](int s) {
        uint2 u = Hv[s * 32 + lane];
        __half2 p0 = *reinterpret_cast<__half2*>(&u.x);
        __half2 p1 = *reinterpret_cast<__half2*>(&u.y);
        float2 f0 = __half22float2(p0);
        float2 f1 = __half22float2(p1);
        acc.x += f0.x; acc.y += f0.y; acc.z += f1.x; acc.w += f1.y;
    };

    int e = beg;
    for (; e + 7 < end; e += 8) {
        int s0 = g_srcsorted[e],   s1 = g_srcsorted[e+1], s2 = g_srcsorted[e+2], s3 = g_srcsorted[e+3];
        int s4 = g_srcsorted[e+4], s5 = g_srcsorted[e+5], s6 = g_srcsorted[e+6], s7 = g_srcsorted[e+7];
        addrow(s0); addrow(s1); addrow(s2); addrow(s3);
        addrow(s4); addrow(s5); addrow(s6); addrow(s7);
    }
    for (; e < end; e++) addrow(g_srcsorted[e]);

    float rs = g_degin[warp];
    float4 b = reinterpret_cast<const float4*>(bias)[lane];
    float4 x;
    x.x = fmaxf(acc.x * rs + b.x, 0.f);
    x.y = fmaxf(acc.y * rs + b.y, 0.f);
    x.z = fmaxf(acc.z * rs + b.z, 0.f);
    x.w = fmaxf(acc.w * rs + b.w, 0.f);
    reinterpret_cast<float4*>(g_X)[warp * 32 + lane] = x;
}

// ---------------------------------------------------------------------------
// weight pre-split: W[K x N] -> bf16 hi/lo [Npad x K] (transposed, padded)
// ---------------------------------------------------------------------------
__global__ void presplit_Wt_kernel(const float* __restrict__ W,
                                   __nv_bfloat16* __restrict__ hi,
                                   __nv_bfloat16* __restrict__ lo,
                                   int K, int N, int Npad) {
    int i = blockIdx.x * blockDim.x + threadIdx.x;
    if (i >= Npad * K) return;
    int n = i / K, k = i - n * K;
    float v = (n < N) ? W[(size_t)k * N + n] : 0.f;
    __nv_bfloat16 h = __float2bfloat16_rn(v);
    float r = v - __bfloat162float(h);
    hi[i] = h;
    lo[i] = __float2bfloat16_rn(r);
}

// ---------------------------------------------------------------------------
// split-BF16 GEMM (3 products: hh + lh + hl): C[M,N] = A[M,K] @ Wt[N x K]
// BM=128, BN=64, BK=32, 256 threads (8 warps: 4m x 2n), warp tile 32x32.
// Output either fp32 C (guarded) or fp16 Chalf (full tile, ldC cols).
// ---------------------------------------------------------------------------
#define OFF_AH   0
#define OFF_AL   10240                    // 128 * 80
#define OFF_BH   20480
#define OFF_BL   25600                    // + 64 * 80
#define STG_BYTES 30720
#define SMEM_TOT (2 * STG_BYTES)          // 61440

__device__ __forceinline__ void cp16(uint32_t saddr, const void* g) {
    asm volatile("cp.async.ca.shared.global [%0], [%1], 16;" :: "r"(saddr), "l"(g) : "memory");
}

__device__ __forceinline__ void ldsm4(uint32_t& r0, uint32_t& r1, uint32_t& r2, uint32_t& r3,
                                      uint32_t saddr) {
    asm volatile("ldmatrix.sync.aligned.m8n8.x4.shared.b16 {%0,%1,%2,%3}, [%4];"
                 : "=r"(r0), "=r"(r1), "=r"(r2), "=r"(r3) : "r"(saddr));
}

__device__ __forceinline__ void mma_bf16(
    float& d0, float& d1, float& d2, float& d3,
    uint32_t a0, uint32_t a1, uint32_t a2, uint32_t a3,
    uint32_t b0, uint32_t b1)
{
    asm volatile(
        "mma.sync.aligned.m16n8k16.row.col.f32.bf16.bf16.f32 "
        "{%0,%1,%2,%3}, {%4,%5,%6,%7}, {%8,%9}, {%0,%1,%2,%3};"
        : "+f"(d0), "+f"(d1), "+f"(d2), "+f"(d3)
        : "r"(a0), "r"(a1), "r"(a2), "r"(a3), "r"(b0), "r"(b1));
}

// pack two floats' bf16 hi parts / lo parts
__device__ __forceinline__ void split_pack2(float x, float y, uint32_t& hi2, uint32_t& lo2) {
    __nv_bfloat162 h = __floats2bfloat162_rn(x, y);
    float rx = x - __bfloat162float(__low2bfloat16(h));
    float ry = y - __bfloat162float(__high2bfloat16(h));
    __nv_bfloat162 l = __floats2bfloat162_rn(rx, ry);
    hi2 = *reinterpret_cast<uint32_t*>(&h);
    lo2 = *reinterpret_cast<uint32_t*>(&l);
}

__global__ __launch_bounds__(256) void mma_gemm_kernel(
    const float* __restrict__ A, int Mvalid,
    const __nv_bfloat16* __restrict__ Bhi, const __nv_bfloat16* __restrict__ Blo, int K,
    float* __restrict__ C, __half* __restrict__ Chalf, int ldC, int Mout, int Nout,
    const float* __restrict__ bias, const float* __restrict__ rowscale)
{
    extern __shared__ uint8_t smem_raw[];
    const uint32_t smem_b = (uint32_t)__cvta_generic_to_shared(smem_raw);

    const int tid  = threadIdx.x;
    const int lane = tid & 31;
    const int warp = tid >> 5;
    const int wm   = warp >> 1;          // 0..3
    const int wn   = warp & 1;           // 0..1
    const int rowBase = blockIdx.y * 128;
    const int colBase = blockIdx.x * 64;
    const int nStages = K >> 5;

    float acc[2][4][4];
    #pragma unroll
    for (int i = 0; i < 2; i++)
        #pragma unroll
        for (int j = 0; j < 4; j++)
            #pragma unroll
            for (int l = 0; l < 4; l++) acc[i][j][l] = 0.f;

    // A loader slots: 4 float4/thread; row = idx>>3, c4 = idx&7 (32 floats/row)
    int aRow[4], aC4[4];
    #pragma unroll
    for (int i = 0; i < 4; i++) {
        int idx = tid + i * 256;
        aRow[i] = idx >> 3;
        aC4[i]  = idx & 7;
    }
    // B loader slot: 1 per thread: n = tid>>2, c16 = tid&3
    const int bN = tid >> 2, bC = tid & 3;

    float4 pa[4];
    auto loadA = [&](int s) {
        const int k0 = s * 32;
        #pragma unroll
        for (int i = 0; i < 4; i++) {
            int gr = rowBase + aRow[i];
            pa[i] = (gr < Mvalid)
                  ? *reinterpret_cast<const float4*>(A + (size_t)gr * K + k0 + aC4[i] * 4)
                  : make_float4(0.f, 0.f, 0.f, 0.f);
        }
    };
    auto storeA = [&](int b) {
        #pragma unroll
        for (int i = 0; i < 4; i++) {
            uint32_t h01, l01, h23, l23;
            split_pack2(pa[i].x, pa[i].y, h01, l01);
            split_pack2(pa[i].z, pa[i].w, h23, l23);
            uint32_t off = aRow[i] * 80 + aC4[i] * 8;
            *reinterpret_cast<uint2*>(smem_raw + off + b * STG_BYTES + OFF_AH) = make_uint2(h01, h23);
            *reinterpret_cast<uint2*>(smem_raw + off + b * STG_BYTES + OFF_AL) = make_uint2(l01, l23);
        }
    };
    auto issueB = [&](int s, int b) {
        const int k0 = s * 32;
        const uint32_t sb = smem_b + b * STG_BYTES;
        size_t g = (size_t)(colBase + bN) * K + k0 + bC * 8;
        uint32_t off = bN * 80 + bC * 16;
        cp16(sb + OFF_BH + off, Bhi + g);
        cp16(sb + OFF_BL + off, Blo + g);
        asm volatile("cp.async.commit_group;" ::: "memory");
    };

    loadA(0);
    issueB(0, 0);

    for (int s = 0; s < nStages; s++) {
        const int b = s & 1;
        storeA(b);
        if (s + 1 < nStages) {
            loadA(s + 1);
            issueB(s + 1, b ^ 1);
            asm volatile("cp.async.wait_group 1;" ::: "memory");
        } else {
            asm volatile("cp.async.wait_group 0;" ::: "memory");
        }
        __syncthreads();

        const uint32_t sAh = smem_b + b * STG_BYTES + OFF_AH;
        const uint32_t sAl = smem_b + b * STG_BYTES + OFF_AL;
        const uint32_t sBh = smem_b + b * STG_BYTES + OFF_BH;
        const uint32_t sBl = smem_b + b * STG_BYTES + OFF_BL;

        // ldmatrix lane address components
        const int aLRow = lane & 15;               // row within 16-row tile
        const int aKoff = (lane >> 4) * 8;         // +8 k for mats 2,3
        const int bLN   = ((lane >> 4) << 3) + (lane & 7);  // n within 16-col pair
        const int bKoff = ((lane >> 3) & 1) * 8;   // +8 k for mats 1,3

        #pragma unroll
        for (int kk = 0; kk < 2; kk++) {
            const int kb = kk * 16;
            uint32_t ah[2][4], al[2][4];
            #pragma unroll
            for (int mt = 0; mt < 2; mt++) {
                int r = (wm * 2 + mt) * 16 + aLRow;
                uint32_t ad = sAh + r * 80 + (kb + aKoff) * 2;
                ldsm4(ah[mt][0], ah[mt][1], ah[mt][2], ah[mt][3], ad);
                ad = sAl + r * 80 + (kb + aKoff) * 2;
                ldsm4(al[mt][0], al[mt][1], al[mt][2], al[mt][3], ad);
            }
            uint32_t bh[2][4], bl[2][4];
            #pragma unroll
            for (int p = 0; p < 2; p++) {
                int n = wn * 32 + p * 16 + bLN;
                uint32_t bd = sBh + n * 80 + (kb + bKoff) * 2;
                ldsm4(bh[p][0], bh[p][1], bh[p][2], bh[p][3], bd);
                bd = sBl + n * 80 + (kb + bKoff) * 2;
                ldsm4(bl[p][0], bl[p][1], bl[p][2], bl[p][3], bd);
            }
            #pragma unroll
            for (int mt = 0; mt < 2; mt++) {
                #pragma unroll
                for (int nt = 0; nt < 4; nt++) {
                    float* d = acc[mt][nt];
                    int p = nt >> 1, q = (nt & 1) * 2;
                    uint32_t b0h = bh[p][q], b1h = bh[p][q + 1];
                    uint32_t b0l = bl[p][q], b1l = bl[p][q + 1];
                    mma_bf16(d[0], d[1], d[2], d[3],
                             ah[mt][0], ah[mt][1], ah[mt][2], ah[mt][3], b0h, b1h);
                    mma_bf16(d[0], d[1], d[2], d[3],
                             al[mt][0], al[mt][1], al[mt][2], al[mt][3], b0h, b1h);
                    mma_bf16(d[0], d[1], d[2], d[3],
                             ah[mt][0], ah[mt][1], ah[mt][2], ah[mt][3], b0l, b1l);
                }
            }
        }
        __syncthreads();
    }

    // epilogue
    #pragma unroll
    for (int mt = 0; mt < 2; mt++) {
        int r0 = rowBase + wm * 32 + mt * 16 + (lane >> 2);
        int r1 = r0 + 8;
        float rs0 = rowscale ? rowscale[r0] : 1.f;
        float rs1 = rowscale ? rowscale[r1] : 1.f;
        #pragma unroll
        for (int nt = 0; nt < 4; nt++) {
            int c0 = colBase + wn * 32 + nt * 8 + (lane & 3) * 2;
            float b0 = (bias && c0 < Nout)     ? bias[c0]     : 0.f;
            float b1 = (bias && c0 + 1 < Nout) ? bias[c0 + 1] : 0.f;
            float v00 = acc[mt][nt][0] * rs0 + b0;
            float v01 = acc[mt][nt][1] * rs0 + b1;
            float v10 = acc[mt][nt][2] * rs1 + b0;
            float v11 = acc[mt][nt][3] * rs1 + b1;
            if (Chalf) {
                // fp16 output: full padded tile always in-bounds
                *reinterpret_cast<__half2*>(Chalf + (size_t)r0 * ldC + c0) = __floats2half2_rn(v00, v01);
                *reinterpret_cast<__half2*>(Chalf + (size_t)r1 * ldC + c0) = __floats2half2_rn(v10, v11);
            } else if (c0 + 1 < Nout) {
                if (r0 < Mout) *reinterpret_cast<float2*>(C + (size_t)r0 * ldC + c0) = make_float2(v00, v01);
                if (r1 < Mout) *reinterpret_cast<float2*>(C + (size_t)r1 * ldC + c0) = make_float2(v10, v11);
            } else if (c0 < Nout) {
                if (r0 < Mout) C[(size_t)r0 * ldC + c0] = v00;
                if (r1 < Mout) C[(size_t)r1 * ldC + c0] = v10;
            }
        }
    }
}

// ---------------------------------------------------------------------------
extern "C" void kernel_launch(void* const* d_in, const int* in_sizes, int n_in,
                              void* d_out, int out_size)
{
    const float* n_feats = (const float*)d_in[0];
    const int*   src     = (const int*)  d_in[1];
    const int*   dst     = (const int*)  d_in[2];
    const float* Wp      = (const float*)d_in[3];
    const float* bp      = (const float*)d_in[4];
    const float* W1      = (const float*)d_in[5];
    const float* b1      = (const float*)d_in[6];
    const float* W2      = (const float*)d_in[7];
    const float* b2      = (const float*)d_in[8];
    const float* Wc      = (const float*)d_in[9];
    const float* bc      = (const float*)d_in[10];
    float* out = (float*)d_out;
    int E = in_sizes[1];

    float *X, *degout;
    __half *Hh;
    __nv_bfloat16 *Wphi, *Wplo, *W1hi, *W1lo, *W2hi, *W2lo, *Wchi, *Wclo;
    cudaGetSymbolAddress((void**)&X, g_X);
    cudaGetSymbolAddress((void**)&Hh, g_Hh);
    cudaGetSymbolAddress((void**)&degout, g_degout);
    cudaGetSymbolAddress((void**)&Wphi, gWp_hi); cudaGetSymbolAddress((void**)&Wplo, gWp_lo);
    cudaGetSymbolAddress((void**)&W1hi, gW1_hi); cudaGetSymbolAddress((void**)&W1lo, gW1_lo);
    cudaGetSymbolAddress((void**)&W2hi, gW2_hi); cudaGetSymbolAddress((void**)&W2lo, gW2_lo);
    cudaGetSymbolAddress((void**)&Wchi, gWc_hi); cudaGetSymbolAddress((void**)&Wclo, gWc_lo);

    // one-time host-side setup (no device allocation)
    static bool init_done = false;
    static cudaStream_t s2 = nullptr;
    static cudaEvent_t evFork, evDeg, evCsr;
    if (!init_done) {
        cudaFuncSetAttribute(mma_gemm_kernel, cudaFuncAttributeMaxDynamicSharedMemorySize,
                             SMEM_TOT);
        cudaStreamCreateWithFlags(&s2, cudaStreamNonBlocking);
        cudaEventCreateWithFlags(&evFork, cudaEventDisableTiming);
        cudaEventCreateWithFlags(&evDeg,  cudaEventDisableTiming);
        cudaEventCreateWithFlags(&evCsr,  cudaEventDisableTiming);
        init_done = true;
    }

    const int T = 256;
    int nodeBlocks = (NPAD + T - 1) / T;
    int edgeBlocks = (E + T - 1) / T;
    int aggBlocks  = (NPAD + 7) / 8;      // 8 warps/block, 1 warp/node

    dim3 gH(2, NPAD / 128);
    dim3 gC(1, NPAD / 128);

    // ---- fork: CSR + degree chain on s2, GEMM chain on stream 0 ----
    cudaEventRecord(evFork, 0);
    cudaStreamWaitEvent(s2, evFork, 0);

    // s2: CSR build
    zero_cnt_kernel<<<nodeBlocks, T, 0, s2>>>();
    count_kernel<<<edgeBlocks, T, 0, s2>>>(src, dst, E);
    rsqrt_kernel<<<nodeBlocks, T, 0, s2>>>();
    cudaEventRecord(evDeg, s2);           // degout/degin ready
    scan_phaseA<<<SCAN_B, T, 0, s2>>>();
    scan_phaseB<<<1, T, 0, s2>>>();
    scan_phaseC<<<SCAN_B, T, 0, s2>>>();
    scatter_kernel<<<edgeBlocks, T, 0, s2>>>(src, dst, E);
    cudaEventRecord(evCsr, s2);           // srcsorted/rowstart ready

    // stream 0: weight pre-split (tiny) + projection GEMM (independent of CSR)
    presplit_Wt_kernel<<<(H_DIM * F_DIM + T - 1) / T, T>>>(Wp, Wphi, Wplo, F_DIM, H_DIM, H_DIM);
    presplit_Wt_kernel<<<(H_DIM * H_DIM + T - 1) / T, T>>>(W1, W1hi, W1lo, H_DIM, H_DIM, H_DIM);
    presplit_Wt_kernel<<<(H_DIM * H_DIM + T - 1) / T, T>>>(W2, W2hi, W2lo, H_DIM, H_DIM, H_DIM);
    presplit_Wt_kernel<<<(CPAD  * H_DIM + T - 1) / T, T>>>(Wc, Wchi, Wclo, H_DIM, C_DIM, CPAD);

    // projection: X = n_feats @ Wp + bp  (fp32 out)
    mma_gemm_kernel<<<gH, T, SMEM_TOT>>>(n_feats, N_NODES, Wphi, Wplo, F_DIM,
                                         X, nullptr, H_DIM, NPAD, H_DIM, bp, nullptr);

    // ---- GCN layer 1 (GEMM needs degout; agg needs CSR) ----
    cudaStreamWaitEvent(0, evDeg, 0);
    mma_gemm_kernel<<<gH, T, SMEM_TOT>>>(X, NPAD, W1hi, W1lo, H_DIM,
                                         nullptr, Hh, H_DIM, NPAD, H_DIM, nullptr, degout);
    cudaStreamWaitEvent(0, evCsr, 0);
    csr_agg_kernel<<<aggBlocks, T>>>(b1);

    // ---- GCN layer 2 ----
    mma_gemm_kernel<<<gH, T, SMEM_TOT>>>(X, NPAD, W2hi, W2lo, H_DIM,
                                         nullptr, Hh, H_DIM, NPAD, H_DIM, nullptr, degout);
    csr_agg_kernel<<<aggBlocks, T>>>(b2);

    // classifier: out = X @ Wc + bc  (fp32 out)
    mma_gemm_kernel<<<gC, T, SMEM_TOT>>>(X, NPAD, Wchi, Wclo, H_DIM,
                                         out, nullptr, C_DIM, N_NODES, C_DIM, bc, nullptr);
}